// round 9
// baseline (speedup 1.0000x reference)
#include <cuda_runtime.h>
#include <cuda_bf16.h>
#include <cstdint>

// ---------------------------------------------------------------------------
// Performer attention. Fixed shapes: B=4, S=4096, Dm=1024, H=16, Dh=64, R=256
// Big GEMMs: split-bf16 (hi/lo) on mma.sync HMMA, 4-stage cp.async pipeline,
// 128x64 CTA tile (32-reg accumulators, no spills), 2 CTAs/SM.
// ---------------------------------------------------------------------------

#define B_    4
#define S_    4096
#define DM    1024
#define H_    16
#define DH    64
#define RR    256
#define MROWS (B_*S_)        // 16384
#define NROWS (B_*S_*H_)     // 262144
#define BH    (B_*H_)        // 64
#define SPLIT 8
#define SCH   (S_/SPLIT)     // 512

#define RATIO 0.0625f                 // 1/sqrt(R)
#define CNORM 0.35355339059327373f    // Dh^{-1/4}

// ------------------------------ scratch ------------------------------------
__device__ float g_q[MROWS*DM];
__device__ float g_k[MROWS*DM];
__device__ float g_v[MROWS*DM];
__device__ float g_qhat[NROWS*RR];
__device__ float g_u[NROWS*RR];
__device__ float g_den[NROWS];
__device__ float g_kvp[SPLIT*BH*RR*DH];
__device__ float g_kvf[BH*RR*DH];
__device__ float g_u1p[SPLIT*BH*RR];
__device__ float g_v1p[SPLIT*BH*DH];
__device__ float g_k1[BH*RR];
__device__ float g_v1[BH*DH];
__device__ float g_kmax;
// bf16 split buffers (reused across the 4 GEMMs)
__device__ __nv_bfloat16 g_ah[MROWS*DM];
__device__ __nv_bfloat16 g_al[MROWS*DM];
__device__ __nv_bfloat16 g_wh[DM*DM];
__device__ __nv_bfloat16 g_wl[DM*DM];

extern __shared__ float dynsm[];

// ------------------------- FMA-pipe exp (no MUFU) --------------------------
__device__ __forceinline__ float fexp(float x)
{
    x = fminf(fmaxf(x, -87.0f), 87.0f);
    float z = x * 1.4426950408889634f;
    float t = z + 12582912.0f;
    int   n = __float_as_int(t) - 0x4B400000;
    float f = z - (t - 12582912.0f);
    float p = 1.3333558e-3f;
    p = fmaf(p, f, 9.6181291e-3f);
    p = fmaf(p, f, 5.5504109e-2f);
    p = fmaf(p, f, 2.4022651e-1f);
    p = fmaf(p, f, 6.9314718e-1f);
    p = fmaf(p, f, 1.0f);
    return p * __int_as_float((n + 127) << 23);
}

__device__ __forceinline__ void atomicMaxF(float* addr, float v)
{
    int* ia = (int*)addr;
    int old = *ia;
    while (__int_as_float(old) < v) {
        int assumed = old;
        old = atomicCAS(ia, assumed, __float_as_int(v));
        if (old == assumed) break;
    }
}

__global__ void k_init() { g_kmax = -3.0e38f; }

// ----------------------- PTX helpers (compute_103-safe) ---------------------
__device__ __forceinline__ uint32_t s2u(const void* p)
{
    uint32_t a;
    asm("{ .reg .u64 t; cvta.to.shared.u64 t, %1; cvt.u32.u64 %0, t; }"
        : "=r"(a) : "l"(p));
    return a;
}
__device__ __forceinline__ void cp16(uint32_t s, const void* g)
{
    asm volatile("cp.async.cg.shared.global [%0], [%1], 16;"
                 :: "r"(s), "l"(g));
}
__device__ __forceinline__ void ldm4(uint32_t* r, uint32_t addr)
{
    asm volatile("ldmatrix.sync.aligned.m8n8.x4.shared.b16 {%0,%1,%2,%3}, [%4];"
                 : "=r"(r[0]), "=r"(r[1]), "=r"(r[2]), "=r"(r[3]) : "r"(addr));
}
__device__ __forceinline__ void mma16816(float* c, const uint32_t* a,
                                         const uint32_t* b)
{
    asm volatile("mma.sync.aligned.m16n8k16.row.col.f32.bf16.bf16.f32 "
                 "{%0,%1,%2,%3}, {%4,%5,%6,%7}, {%8,%9}, {%0,%1,%2,%3};"
                 : "+f"(c[0]), "+f"(c[1]), "+f"(c[2]), "+f"(c[3])
                 : "r"(a[0]), "r"(a[1]), "r"(a[2]), "r"(a[3]),
                   "r"(b[0]), "r"(b[1]));
}
__device__ __forceinline__ uint32_t pack2(float a, float b)
{
    return (uint32_t)__bfloat16_as_ushort(__float2bfloat16(a))
         | ((uint32_t)__bfloat16_as_ushort(__float2bfloat16(b)) << 16);
}

// ------------------------ split-bf16 conversion -----------------------------
__global__ __launch_bounds__(256)
void k_cvt_act(const float4* __restrict__ X, uint2* __restrict__ Hh,
               uint2* __restrict__ Hl)
{
    const int i = blockIdx.x * 256 + threadIdx.x;
    float4 x = X[i];
    uint32_t hx = __bfloat16_as_ushort(__float2bfloat16(x.x));
    uint32_t hy = __bfloat16_as_ushort(__float2bfloat16(x.y));
    uint32_t hz = __bfloat16_as_ushort(__float2bfloat16(x.z));
    uint32_t hw = __bfloat16_as_ushort(__float2bfloat16(x.w));
    float rx = x.x - __bfloat162float(__ushort_as_bfloat16((unsigned short)hx));
    float ry = x.y - __bfloat162float(__ushort_as_bfloat16((unsigned short)hy));
    float rz = x.z - __bfloat162float(__ushort_as_bfloat16((unsigned short)hz));
    float rw = x.w - __bfloat162float(__ushort_as_bfloat16((unsigned short)hw));
    uint32_t lx = __bfloat16_as_ushort(__float2bfloat16(rx));
    uint32_t ly = __bfloat16_as_ushort(__float2bfloat16(ry));
    uint32_t lz = __bfloat16_as_ushort(__float2bfloat16(rz));
    uint32_t lw = __bfloat16_as_ushort(__float2bfloat16(rw));
    uint2 h; h.x = hx | (hy << 16); h.y = hz | (hw << 16);
    uint2 l; l.x = lx | (ly << 16); l.y = lz | (lw << 16);
    Hh[i] = h; Hl[i] = l;
}

// W[k][n] -> Th/Tl[n][k] (transpose + split), 32x32 tiles
__global__ void k_cvt_wt(const float* __restrict__ W, __nv_bfloat16* __restrict__ Th,
                         __nv_bfloat16* __restrict__ Tl)
{
    __shared__ float t[32][33];
    const int n0 = blockIdx.x * 32, k0 = blockIdx.y * 32;
    const int tx = threadIdx.x, ty = threadIdx.y;
    #pragma unroll
    for (int j = 0; j < 32; j += 8)
        t[ty + j][tx] = W[(size_t)(k0 + ty + j) * DM + n0 + tx];
    __syncthreads();
    #pragma unroll
    for (int j = 0; j < 32; j += 8) {
        float v = t[tx][ty + j];
        __nv_bfloat16 h = __float2bfloat16(v);
        Th[(size_t)(n0 + ty + j) * DM + k0 + tx] = h;
        Tl[(size_t)(n0 + ty + j) * DM + k0 + tx] =
            __float2bfloat16(v - __bfloat162float(h));
    }
}

// -------------- HMMA GEMM: C[16384,1024] = A @ B^T (+bias) ------------------
// 128x64 tile/CTA, 256 thr (8 warps: 2m x 4n, 64x16/warp), K-chunk 16,
// 4-stage cp.async pipeline (72 KB), 2 CTAs/SM, ~90 regs (no spills).
#define MCHK  16
#define NCHK  (DM / MCHK)          // 64 chunks
#define MATA  (128 * 48)           // 128x16 bf16 tile, 48B row stride (6144)
#define MATB2 (64 * 48)            // 64x16 bf16 tile (3072)
#define STG   (2*MATA + 2*MATB2)   // 18432 per stage (Ah, Al, Bh, Bl)
#define MM_SMEM (4 * STG)          // 73728 B

__global__ __launch_bounds__(256, 2)
void k_mm(const __nv_bfloat16* __restrict__ Ah, const __nv_bfloat16* __restrict__ Al,
          const __nv_bfloat16* __restrict__ Bh, const __nv_bfloat16* __restrict__ Bl,
          const float* __restrict__ bias, float* __restrict__ C)
{
    const uint32_t smb = s2u(dynsm);
    const int tid = threadIdx.x, wid = tid >> 5, lane = tid & 31;
    const int bx = blockIdx.x, by = blockIdx.y;
    const int wm = wid & 1, wn = wid >> 1;

    // loader: 3 x 16B per thread per chunk (768 total: 256 Ah,Al rows + 128 B)
    const __nv_bfloat16* gp[3];
    uint32_t soff[3];
    #pragma unroll
    for (int t = 0; t < 3; t++) {
        int idx = tid + t * 256;
        int q = idx & 1, r = idx >> 1;
        if (r < 256) {
            int mat = r >> 7, row = r & 127;
            gp[t] = (mat ? Al : Ah) + (size_t)(by * 128 + row) * DM + q * 8;
            soff[t] = (uint32_t)(mat * MATA + row * 48 + q * 16);
        } else {
            int rb = r - 256;
            int mat = rb >> 6, row = rb & 63;
            gp[t] = (mat ? Bl : Bh) + (size_t)(bx * 64 + row) * DM + q * 8;
            soff[t] = (uint32_t)(2 * MATA + mat * MATB2 + row * 48 + q * 16);
        }
    }

    auto issue = [&](int c) {
        const int k0 = c * MCHK;
        const uint32_t sb = smb + (uint32_t)(c & 3) * STG;
        #pragma unroll
        for (int t = 0; t < 3; t++)
            cp16(sb + soff[t], gp[t] + k0);
        asm volatile("cp.async.commit_group;");
    };

    issue(0); issue(1); issue(2);

    const int part = lane >> 3, l8 = lane & 7;
    const int aRow = (part & 1) * 8 + l8, aCol = (part >> 1) * 8;
    const int bRow = (part >> 1) * 8 + l8, bCol = (part & 1) * 8;
    uint32_t aoff[4];
    #pragma unroll
    for (int mi = 0; mi < 4; mi++)
        aoff[mi] = (uint32_t)((wm * 64 + mi * 16 + aRow) * 48 + aCol * 2);
    const uint32_t boff = (uint32_t)(2 * MATA + (wn * 16 + bRow) * 48 + bCol * 2);

    float acc[4][2][4] = {};

    for (int c = 0; c < NCHK; c++) {
        asm volatile("cp.async.wait_group 2;");
        __syncthreads();
        if (c + 3 < NCHK) issue(c + 3);

        const uint32_t sb = smb + (uint32_t)(c & 3) * STG;
        uint32_t ah[16], al[16], bh[4], bl[4];
        #pragma unroll
        for (int mi = 0; mi < 4; mi++) {
            ldm4(&ah[mi * 4], sb + aoff[mi]);
            ldm4(&al[mi * 4], sb + MATA + aoff[mi]);
        }
        ldm4(bh, sb + boff);
        ldm4(bl, sb + MATB2 + boff);

        #pragma unroll
        for (int mi = 0; mi < 4; mi++)
            #pragma unroll
            for (int ni = 0; ni < 2; ni++) {
                mma16816(acc[mi][ni], &ah[mi * 4], &bh[ni * 2]);
                mma16816(acc[mi][ni], &ah[mi * 4], &bl[ni * 2]);
                mma16816(acc[mi][ni], &al[mi * 4], &bh[ni * 2]);
            }
    }

    const int g = lane >> 2, cc = (lane & 3) * 2;
    #pragma unroll
    for (int mi = 0; mi < 4; mi++) {
        const int r0 = by * 128 + wm * 64 + mi * 16 + g;
        #pragma unroll
        for (int ni = 0; ni < 2; ni++) {
            const int col = bx * 64 + wn * 16 + ni * 8 + cc;
            const float b0 = bias[col], b1 = bias[col + 1];
            float2 o0, o1;
            o0.x = acc[mi][ni][0] + b0; o0.y = acc[mi][ni][1] + b1;
            o1.x = acc[mi][ni][2] + b0; o1.y = acc[mi][ni][3] + b1;
            *(float2*)(C + (size_t)r0 * DM + col)       = o0;
            *(float2*)(C + (size_t)(r0 + 8) * DM + col) = o1;
        }
    }
}

// ------------------- FAVOR+ feature kernel (q or k) -------------------------
#define FEAT_SMEM ((64*256 + 8*4*64) * 4)

template <bool IS_Q>
__global__ __launch_bounds__(256)
void k_feat(const float* __restrict__ X, const float* __restrict__ proj,
            float* __restrict__ out, const float* __restrict__ k1,
            float* __restrict__ den)
{
    float* sm = dynsm;
    float* projT = sm;
    float* sq    = sm + 64 * 256;
    const int tid = threadIdx.x;
    const int w = tid >> 5, l = tid & 31;

    for (int i = tid; i < 64 * 256; i += 256) {
        int k = i >> 8, r = i & 255;
        projT[i] = CNORM * proj[r * 64 + k];
    }
    __syncthreads();

    const float4* pT = (const float4*)projT;
    float* sqw = sq + w * 4 * 64;
    float wmax = -3.0e38f;
    const int jrow = l >> 3;
    const int off  = (l & 7) * 8;
    const int base = blockIdx.x * 512 + w * 64;

    for (int it = 0; it < 16; it++) {
        const int n0 = base + it * 4;
        const float* xp = X + (n0 + jrow) * 64 + off;
        float4 xa = *(const float4*)xp;
        float4 xb = *(const float4*)(xp + 4);
        float ss = xa.x*xa.x + xa.y*xa.y + xa.z*xa.z + xa.w*xa.w
                 + xb.x*xb.x + xb.y*xb.y + xb.z*xb.z + xb.w*xb.w;
        ss += __shfl_xor_sync(0xffffffffu, ss, 1);
        ss += __shfl_xor_sync(0xffffffffu, ss, 2);
        ss += __shfl_xor_sync(0xffffffffu, ss, 4);
        float diagl = 0.0625f * ss;
        float diag[4];
        #pragma unroll
        for (int j = 0; j < 4; j++)
            diag[j] = __shfl_sync(0xffffffffu, diagl, j * 8);

        __syncwarp();
        *(float4*)&sqw[jrow * 64 + off]     = xa;
        *(float4*)&sqw[jrow * 64 + off + 4] = xb;
        __syncwarp();

        float4 a0[4] = {}, a1[4] = {};
        #pragma unroll 2
        for (int k = 0; k < 64; k++) {
            float4 p0 = pT[k * 64 + l];
            float4 p1 = pT[k * 64 + 32 + l];
            #pragma unroll
            for (int j = 0; j < 4; j++) {
                float qk = sqw[j * 64 + k];
                a0[j].x = fmaf(qk, p0.x, a0[j].x);
                a0[j].y = fmaf(qk, p0.y, a0[j].y);
                a0[j].z = fmaf(qk, p0.z, a0[j].z);
                a0[j].w = fmaf(qk, p0.w, a0[j].w);
                a1[j].x = fmaf(qk, p1.x, a1[j].x);
                a1[j].y = fmaf(qk, p1.y, a1[j].y);
                a1[j].z = fmaf(qk, p1.z, a1[j].z);
                a1[j].w = fmaf(qk, p1.w, a1[j].w);
            }
        }
        #pragma unroll
        for (int j = 0; j < 4; j++) {
            const int n = n0 + j;
            float* op = out + n * 256 + 4 * l;
            float lm = fmaxf(fmaxf(fmaxf(a0[j].x, a0[j].y), fmaxf(a0[j].z, a0[j].w)),
                             fmaxf(fmaxf(a1[j].x, a1[j].y), fmaxf(a1[j].z, a1[j].w)));
            if (IS_Q) {
                #pragma unroll
                for (int o = 16; o > 0; o >>= 1)
                    lm = fmaxf(lm, __shfl_xor_sync(0xffffffffu, lm, o));
                const float sub = diag[j] + lm;
                float4 w0, w1;
                w0.x = RATIO * (fexp(a0[j].x - sub) + 1e-4f);
                w0.y = RATIO * (fexp(a0[j].y - sub) + 1e-4f);
                w0.z = RATIO * (fexp(a0[j].z - sub) + 1e-4f);
                w0.w = RATIO * (fexp(a0[j].w - sub) + 1e-4f);
                w1.x = RATIO * (fexp(a1[j].x - sub) + 1e-4f);
                w1.y = RATIO * (fexp(a1[j].y - sub) + 1e-4f);
                w1.z = RATIO * (fexp(a1[j].z - sub) + 1e-4f);
                w1.w = RATIO * (fexp(a1[j].w - sub) + 1e-4f);
                *(float4*)op         = w0;
                *(float4*)(op + 128) = w1;
                const int bh = ((n >> 16) << 4) | (n & 15);
                const float* kp = k1 + bh * 256 + 4 * l;
                float4 c0 = *(const float4*)kp;
                float4 c1 = *(const float4*)(kp + 128);
                float dp = w0.x*c0.x + w0.y*c0.y + w0.z*c0.z + w0.w*c0.w
                         + w1.x*c1.x + w1.y*c1.y + w1.z*c1.z + w1.w*c1.w;
                #pragma unroll
                for (int o = 16; o > 0; o >>= 1)
                    dp += __shfl_xor_sync(0xffffffffu, dp, o);
                if (l == 0) den[n] = dp;
            } else {
                wmax = fmaxf(wmax, lm);
                const float sub = diag[j];
                float4 w0, w1;
                w0.x = fexp(a0[j].x - sub);
                w0.y = fexp(a0[j].y - sub);
                w0.z = fexp(a0[j].z - sub);
                w0.w = fexp(a0[j].w - sub);
                w1.x = fexp(a1[j].x - sub);
                w1.y = fexp(a1[j].y - sub);
                w1.z = fexp(a1[j].z - sub);
                w1.w = fexp(a1[j].w - sub);
                *(float4*)op         = w0;
                *(float4*)(op + 128) = w1;
            }
        }
    }
    if (!IS_Q) {
        #pragma unroll
        for (int o = 16; o > 0; o >>= 1)
            wmax = fmaxf(wmax, __shfl_xor_sync(0xffffffffu, wmax, o));
        __syncthreads();
        if (l == 0) sm[w] = wmax;
        __syncthreads();
        if (tid == 0) {
            float m = sm[0];
            #pragma unroll
            for (int i = 1; i < 8; i++) m = fmaxf(m, sm[i]);
            atomicMaxF(&g_kmax, m);
        }
    }
}

// --------- kv partials: per (bh, S-chunk) compute u^T @ v [256 x 64] --------
__global__ __launch_bounds__(256)
void k_kv()
{
    __shared__ float Us[16][256];
    __shared__ float Vs[16][64];
    const int bh = blockIdx.x, c = blockIdx.y;
    const int b = bh >> 4, h = bh & 15;
    const int tid = threadIdx.x;
    const int ls = tid >> 4, lr = (tid & 15) * 16;
    const int lv = (tid & 15) * 4;
    const int tr = (tid >> 3) * 8, tv = (tid & 7) * 8;
    const float* ub = g_u + ((b * S_ + c * SCH) * H_ + h) * RR;
    const float* vb = g_v + (b * S_ + c * SCH) * DM + h * DH;

    float acc[8][8] = {};
    float uacc = 0.f, vacc = 0.f;
    for (int s0 = 0; s0 < SCH; s0 += 16) {
        const float* up = ub + (s0 + ls) * (H_ * RR) + lr;
        *(float4*)&Us[ls][lr]      = *(const float4*)(up);
        *(float4*)&Us[ls][lr + 4]  = *(const float4*)(up + 4);
        *(float4*)&Us[ls][lr + 8]  = *(const float4*)(up + 8);
        *(float4*)&Us[ls][lr + 12] = *(const float4*)(up + 12);
        *(float4*)&Vs[ls][lv] = *(const float4*)(vb + (s0 + ls) * DM + lv);
        __syncthreads();
        #pragma unroll
        for (int s = 0; s < 16; s++) {
            float ua[8], va[8];
            *(float4*)&ua[0] = *(const float4*)&Us[s][tr];
            *(float4*)&ua[4] = *(const float4*)&Us[s][tr + 4];
            *(float4*)&va[0] = *(const float4*)&Vs[s][tv];
            *(float4*)&va[4] = *(const float4*)&Vs[s][tv + 4];
            #pragma unroll
            for (int i = 0; i < 8; i++)
                #pragma unroll
                for (int j = 0; j < 8; j++)
                    acc[i][j] = fmaf(ua[i], va[j], acc[i][j]);
            uacc += Us[s][tid];
            if (tid < 64) vacc += Vs[s][tid];
        }
        __syncthreads();
    }
    const int pb = c * BH + bh;
    float* kp = g_kvp + pb * (RR * DH);
    #pragma unroll
    for (int i = 0; i < 8; i++) {
        *(float4*)&kp[(tr + i) * DH + tv]     = *(float4*)&acc[i][0];
        *(float4*)&kp[(tr + i) * DH + tv + 4] = *(float4*)&acc[i][4];
    }
    g_u1p[pb * RR + tid] = uacc;
    if (tid < 64) g_v1p[pb * DH + tid] = vacc;
}

__global__ void k_red()
{
    const int bh = blockIdx.x, t = threadIdx.x;
    const float a = RATIO * fexp(-g_kmax);
    float s = 0.f;
    #pragma unroll
    for (int c = 0; c < SPLIT; c++) s += g_u1p[(c * BH + bh) * RR + t];
    g_k1[bh * RR + t] = a * s + RATIO * 1e-4f * (float)S_;
    if (t < DH) {
        float vs = 0.f;
        #pragma unroll
        for (int c = 0; c < SPLIT; c++) vs += g_v1p[(c * BH + bh) * DH + t];
        g_v1[bh * DH + t] = vs;
    }
}

__global__ void k_kvred()
{
    const int bh = blockIdx.x, r = blockIdx.y, v = threadIdx.x;
    const float a = RATIO * fexp(-g_kmax);
    float s = 0.f;
    #pragma unroll
    for (int c = 0; c < SPLIT; c++)
        s += g_kvp[((c * BH + bh) * RR + r) * DH + v];
    g_kvf[(bh * RR + r) * DH + v] = a * s + RATIO * 1e-4f * g_v1[bh * DH + v];
}

// ----- attention out: qhat[128,256] @ kvf[256,64], /denom, emit bf16 hi/lo --
__global__ __launch_bounds__(256)
void k_att()
{
    __shared__ float As[16][128];
    __shared__ float Bs[16][64];
    const int bh = blockIdx.x, sc = blockIdx.y;
    const int b = bh >> 4, h = bh & 15;
    const int tid = threadIdx.x;
    const int srow = tid >> 1, kcol = (tid & 1) * 8;
    const int krow = tid >> 4, vcol = (tid & 15) * 4;
    const int ts = (tid >> 3) * 4, tv = (tid & 7) * 8;
    const int s_base = sc * 128;
    const float* qb  = g_qhat + ((b * S_ + s_base) * H_ + h) * RR;
    const float* kvb = g_kvf + bh * (RR * DH);

    float acc[4][8] = {};
    for (int k0 = 0; k0 < RR; k0 += 16) {
        const float* qp = qb + srow * (H_ * RR) + k0 + kcol;
        float4 qa = *(const float4*)qp;
        float4 qc = *(const float4*)(qp + 4);
        As[kcol + 0][srow] = qa.x;
        As[kcol + 1][srow] = qa.y;
        As[kcol + 2][srow] = qa.z;
        As[kcol + 3][srow] = qa.w;
        As[kcol + 4][srow] = qc.x;
        As[kcol + 5][srow] = qc.y;
        As[kcol + 6][srow] = qc.z;
        As[kcol + 7][srow] = qc.w;
        *(float4*)&Bs[krow][vcol] = *(const float4*)(kvb + (k0 + krow) * DH + vcol);
        __syncthreads();
        #pragma unroll
        for (int k = 0; k < 16; k++) {
            float a4[4], b8[8];
            a4[0] = As[k][ts + 0];
            a4[1] = As[k][ts + 1];
            a4[2] = As[k][ts + 2];
            a4[3] = As[k][ts + 3];
            *(float4*)&b8[0] = *(const float4*)&Bs[k][tv];
            *(float4*)&b8[4] = *(const float4*)&Bs[k][tv + 4];
            #pragma unroll
            for (int i = 0; i < 4; i++)
                #pragma unroll
                for (int j = 0; j < 8; j++)
                    acc[i][j] = fmaf(a4[i], b8[j], acc[i][j]);
        }
        __syncthreads();
    }
    #pragma unroll
    for (int i = 0; i < 4; i++) {
        const int s = s_base + ts + i;
        const int n = (b * S_ + s) * H_ + h;
        const float inv = 1.0f / g_den[n];
        const size_t ob = (size_t)(b * S_ + s) * DM + h * DH + tv;
        float v[8];
        #pragma unroll
        for (int j = 0; j < 8; j++) v[j] = acc[i][j] * inv;
        float hi[8], lo[8];
        #pragma unroll
        for (int j = 0; j < 8; j++) {
            __nv_bfloat16 hb = __float2bfloat16(v[j]);
            hi[j] = __bfloat162float(hb);
            lo[j] = v[j] - hi[j];
        }
        uint4 ph, pl;
        ph.x = pack2(hi[0], hi[1]); ph.y = pack2(hi[2], hi[3]);
        ph.z = pack2(hi[4], hi[5]); ph.w = pack2(hi[6], hi[7]);
        pl.x = pack2(lo[0], lo[1]); pl.y = pack2(lo[2], lo[3]);
        pl.z = pack2(lo[4], lo[5]); pl.w = pack2(lo[6], lo[7]);
        *(uint4*)(g_ah + ob) = ph;
        *(uint4*)(g_al + ob) = pl;
    }
}

// ---------------------------------------------------------------------------
extern "C" void kernel_launch(void* const* d_in, const int* in_sizes, int n_in,
                              void* d_out, int out_size)
{
    const float* query = (const float*)d_in[0];
    const float* key   = (const float*)d_in[1];
    const float* value = (const float*)d_in[2];
    const float* Wq    = (const float*)d_in[3];
    const float* bq    = (const float*)d_in[4];
    const float* Wk    = (const float*)d_in[5];
    const float* bk    = (const float*)d_in[6];
    const float* Wv    = (const float*)d_in[7];
    const float* bv    = (const float*)d_in[8];
    const float* Wo    = (const float*)d_in[9];
    const float* bo    = (const float*)d_in[10];
    const float* proj  = (const float*)d_in[11];
    float* out = (float*)d_out;

    void *pq, *pk, *pv, *pqh, *pu, *pk1, *pden, *pah, *pal, *pwh, *pwl;
    cudaGetSymbolAddress(&pq,  g_q);
    cudaGetSymbolAddress(&pk,  g_k);
    cudaGetSymbolAddress(&pv,  g_v);
    cudaGetSymbolAddress(&pqh, g_qhat);
    cudaGetSymbolAddress(&pu,  g_u);
    cudaGetSymbolAddress(&pk1, g_k1);
    cudaGetSymbolAddress(&pden, g_den);
    cudaGetSymbolAddress(&pah, g_ah);
    cudaGetSymbolAddress(&pal, g_al);
    cudaGetSymbolAddress(&pwh, g_wh);
    cudaGetSymbolAddress(&pwl, g_wl);

    cudaFuncSetAttribute(k_feat<true>,  cudaFuncAttributeMaxDynamicSharedMemorySize, FEAT_SMEM);
    cudaFuncSetAttribute(k_feat<false>, cudaFuncAttributeMaxDynamicSharedMemorySize, FEAT_SMEM);
    cudaFuncSetAttribute(k_mm, cudaFuncAttributeMaxDynamicSharedMemorySize, MM_SMEM);

    __nv_bfloat16* ah = (__nv_bfloat16*)pah;
    __nv_bfloat16* al = (__nv_bfloat16*)pal;
    __nv_bfloat16* wh = (__nv_bfloat16*)pwh;
    __nv_bfloat16* wl = (__nv_bfloat16*)pwl;

    const int CVT_G = MROWS * DM / 4 / 256;     // 16384
    const dim3 WT_G(DM / 32, DM / 32);          // (32, 32)
    const dim3 WT_B(32, 8);
    const dim3 MM_G(DM / 64, MROWS / 128);      // (16, 128)

    k_init<<<1, 1>>>();

    // Q = query @ Wq + bq
    k_cvt_act<<<CVT_G, 256>>>((const float4*)query, (uint2*)ah, (uint2*)al);
    k_cvt_wt<<<WT_G, WT_B>>>(Wq, wh, wl);
    k_mm<<<MM_G, 256, MM_SMEM>>>(ah, al, wh, wl, bq, (float*)pq);
    // K = key @ Wk + bk
    k_cvt_act<<<CVT_G, 256>>>((const float4*)key, (uint2*)ah, (uint2*)al);
    k_cvt_wt<<<WT_G, WT_B>>>(Wk, wh, wl);
    k_mm<<<MM_G, 256, MM_SMEM>>>(ah, al, wh, wl, bk, (float*)pk);
    // V = value @ Wv + bv
    k_cvt_act<<<CVT_G, 256>>>((const float4*)value, (uint2*)ah, (uint2*)al);
    k_cvt_wt<<<WT_G, WT_B>>>(Wv, wh, wl);
    k_mm<<<MM_G, 256, MM_SMEM>>>(ah, al, wh, wl, bv, (float*)pv);

    // key feature path first (global max + k1 before fused q/denom kernel)
    k_feat<false><<<NROWS / 512, 256, FEAT_SMEM>>>((const float*)pk, proj,
                                                   (float*)pu, nullptr, nullptr);
    k_kv<<<dim3(BH, SPLIT), 256>>>();
    k_red<<<BH, 256>>>();
    k_kvred<<<dim3(BH, RR), DH>>>();

    k_feat<true><<<NROWS / 512, 256, FEAT_SMEM>>>((const float*)pq, proj,
                                                  (float*)pqh, (const float*)pk1,
                                                  (float*)pden);
    k_att<<<dim3(BH, S_ / 128), 256>>>();   // writes split-bf16 into g_ah/g_al

    // out = att @ Wo + bo
    k_cvt_wt<<<WT_G, WT_B>>>(Wo, wh, wl);
    k_mm<<<MM_G, 256, MM_SMEM>>>(ah, al, wh, wl, bo, out);
}

// round 11
// speedup vs baseline: 1.0925x; 1.0925x over previous
#include <cuda_runtime.h>
#include <cuda_bf16.h>
#include <cstdint>

// ---------------------------------------------------------------------------
// Performer attention. Fixed shapes: B=4, S=4096, Dm=1024, H=16, Dh=64, R=256
// Big GEMMs: split-bf16 (hi/lo) on mma.sync HMMA (R6 measured-best geometry).
// u / qhat stored as bf16 (halves feature/kv/att memory traffic).
// ---------------------------------------------------------------------------

#define B_    4
#define S_    4096
#define DM    1024
#define H_    16
#define DH    64
#define RR    256
#define MROWS (B_*S_)        // 16384
#define NROWS (B_*S_*H_)     // 262144
#define BH    (B_*H_)        // 64
#define SPLIT 8
#define SCH   (S_/SPLIT)     // 512

#define RATIO 0.0625f                 // 1/sqrt(R)
#define CNORM 0.35355339059327373f    // Dh^{-1/4}

// ------------------------------ scratch ------------------------------------
__device__ float g_q[MROWS*DM];
__device__ float g_k[MROWS*DM];
__device__ float g_v[MROWS*DM];
__device__ __nv_bfloat16 g_qhat[NROWS*RR];   // bf16 q features
__device__ __nv_bfloat16 g_u[NROWS*RR];      // bf16 exp(dh - diag) for keys
__device__ float g_den[NROWS];
__device__ float g_kvp[SPLIT*BH*RR*DH];
__device__ float g_kvf[BH*RR*DH];
__device__ float g_u1p[SPLIT*BH*RR];
__device__ float g_v1p[SPLIT*BH*DH];
__device__ float g_k1[BH*RR];
__device__ float g_v1[BH*DH];
__device__ float g_kmax;
// bf16 split buffers (reused across the 4 GEMMs)
__device__ __nv_bfloat16 g_ah[MROWS*DM];
__device__ __nv_bfloat16 g_al[MROWS*DM];
__device__ __nv_bfloat16 g_wh[DM*DM];
__device__ __nv_bfloat16 g_wl[DM*DM];

extern __shared__ float dynsm[];

// ------------------------- FMA-pipe exp (no MUFU) --------------------------
__device__ __forceinline__ float fexp(float x)
{
    x = fminf(fmaxf(x, -87.0f), 87.0f);
    float z = x * 1.4426950408889634f;
    float t = z + 12582912.0f;
    int   n = __float_as_int(t) - 0x4B400000;
    float f = z - (t - 12582912.0f);
    float p = 1.3333558e-3f;
    p = fmaf(p, f, 9.6181291e-3f);
    p = fmaf(p, f, 5.5504109e-2f);
    p = fmaf(p, f, 2.4022651e-1f);
    p = fmaf(p, f, 6.9314718e-1f);
    p = fmaf(p, f, 1.0f);
    return p * __int_as_float((n + 127) << 23);
}

__device__ __forceinline__ void atomicMaxF(float* addr, float v)
{
    int* ia = (int*)addr;
    int old = *ia;
    while (__int_as_float(old) < v) {
        int assumed = old;
        old = atomicCAS(ia, assumed, __float_as_int(v));
        if (old == assumed) break;
    }
}

__global__ void k_init() { g_kmax = -3.0e38f; }

// ----------------------- PTX helpers (compute_103-safe) ---------------------
__device__ __forceinline__ uint32_t s2u(const void* p)
{
    uint32_t a;
    asm("{ .reg .u64 t; cvta.to.shared.u64 t, %1; cvt.u32.u64 %0, t; }"
        : "=r"(a) : "l"(p));
    return a;
}
__device__ __forceinline__ void cp16(uint32_t s, const void* g)
{
    asm volatile("cp.async.cg.shared.global [%0], [%1], 16;"
                 :: "r"(s), "l"(g));
}
__device__ __forceinline__ void ldm4(uint32_t* r, uint32_t addr)
{
    asm volatile("ldmatrix.sync.aligned.m8n8.x4.shared.b16 {%0,%1,%2,%3}, [%4];"
                 : "=r"(r[0]), "=r"(r[1]), "=r"(r[2]), "=r"(r[3]) : "r"(addr));
}
__device__ __forceinline__ void mma16816(float* c, const uint32_t* a,
                                         const uint32_t* b)
{
    asm volatile("mma.sync.aligned.m16n8k16.row.col.f32.bf16.bf16.f32 "
                 "{%0,%1,%2,%3}, {%4,%5,%6,%7}, {%8,%9}, {%0,%1,%2,%3};"
                 : "+f"(c[0]), "+f"(c[1]), "+f"(c[2]), "+f"(c[3])
                 : "r"(a[0]), "r"(a[1]), "r"(a[2]), "r"(a[3]),
                   "r"(b[0]), "r"(b[1]));
}
__device__ __forceinline__ uint32_t pack2(float a, float b)
{
    return (uint32_t)__bfloat16_as_ushort(__float2bfloat16(a))
         | ((uint32_t)__bfloat16_as_ushort(__float2bfloat16(b)) << 16);
}
__device__ __forceinline__ float rbf(float x)   // round through bf16
{
    return __bfloat162float(__float2bfloat16(x));
}
__device__ __forceinline__ float2 u2f(uint32_t u)
{
    __nv_bfloat162 h = *(__nv_bfloat162*)&u;
    return __bfloat1622float2(h);
}

// ------------------------ split-bf16 conversion -----------------------------
__global__ __launch_bounds__(256)
void k_cvt_act(const float4* __restrict__ X, uint2* __restrict__ Hh,
               uint2* __restrict__ Hl)
{
    const int i = blockIdx.x * 256 + threadIdx.x;
    float4 x = X[i];
    float hx = rbf(x.x), hy = rbf(x.y), hz = rbf(x.z), hw = rbf(x.w);
    uint2 h; h.x = pack2(hx, hy); h.y = pack2(hz, hw);
    uint2 l; l.x = pack2(x.x - hx, x.y - hy); l.y = pack2(x.z - hz, x.w - hw);
    Hh[i] = h; Hl[i] = l;
}

// W[k][n] -> Th/Tl[n][k] (transpose + split), 32x32 tiles
__global__ void k_cvt_wt(const float* __restrict__ W, __nv_bfloat16* __restrict__ Th,
                         __nv_bfloat16* __restrict__ Tl)
{
    __shared__ float t[32][33];
    const int n0 = blockIdx.x * 32, k0 = blockIdx.y * 32;
    const int tx = threadIdx.x, ty = threadIdx.y;
    #pragma unroll
    for (int j = 0; j < 32; j += 8)
        t[ty + j][tx] = W[(size_t)(k0 + ty + j) * DM + n0 + tx];
    __syncthreads();
    #pragma unroll
    for (int j = 0; j < 32; j += 8) {
        float v = t[tx][ty + j];
        __nv_bfloat16 h = __float2bfloat16(v);
        Th[(size_t)(n0 + ty + j) * DM + k0 + tx] = h;
        Tl[(size_t)(n0 + ty + j) * DM + k0 + tx] =
            __float2bfloat16(v - __bfloat162float(h));
    }
}

// -------------- HMMA GEMM: C[16384,1024] = A @ B^T (+bias) ------------------
// R6 measured-best: 128x128 tile/CTA, 256 thr (8 warps: 2m x 4n, 64x32/warp),
// K-chunk 32, 3-stage cp.async pipeline (120 KB), 1 CTA/SM.
#define MCHK  32
#define NCHK  (DM / MCHK)          // 32 chunks
#define MAT   (128 * 80)           // one 128x32 bf16 tile, 80B row stride
#define STG   (4 * MAT)            // Ah, Al, Bh, Bl
#define MM_SMEM (3 * STG)          // 122880 B

__global__ __launch_bounds__(256)
void k_mm(const __nv_bfloat16* __restrict__ Ah, const __nv_bfloat16* __restrict__ Al,
          const __nv_bfloat16* __restrict__ Bh, const __nv_bfloat16* __restrict__ Bl,
          const float* __restrict__ bias, float* __restrict__ C)
{
    const uint32_t smb = s2u(dynsm);
    const int tid = threadIdx.x, wid = tid >> 5, lane = tid & 31;
    const int bx = blockIdx.x, by = blockIdx.y;
    const int wm = wid & 1, wn = wid >> 1;

    const __nv_bfloat16* gbase[4];
    gbase[0] = Ah + (size_t)(by * 128) * DM;
    gbase[1] = Al + (size_t)(by * 128) * DM;
    gbase[2] = Bh + (size_t)(bx * 128) * DM;
    gbase[3] = Bl + (size_t)(bx * 128) * DM;

    // per-thread loader coords: 8 x 16B per chunk (2048 total / 256 thr)
    int lmat[8], lrow[8], lq[8];
    #pragma unroll
    for (int t = 0; t < 8; t++) {
        int idx = tid + t * 256;
        lmat[t] = idx >> 9;
        lrow[t] = (idx >> 2) & 127;
        lq[t]   = idx & 3;
    }

    auto issue = [&](int c, int s) {
        const int k0 = c * MCHK;
        #pragma unroll
        for (int t = 0; t < 8; t++) {
            const __nv_bfloat16* gp = gbase[lmat[t]] + (size_t)lrow[t] * DM
                                      + k0 + lq[t] * 8;
            uint32_t sa = smb + s * STG + lmat[t] * MAT + lrow[t] * 80 + lq[t] * 16;
            cp16(sa, gp);
        }
        asm volatile("cp.async.commit_group;");
    };

    issue(0, 0);
    issue(1, 1);
    issue(2, 2);

    const int part = lane >> 3, l8 = lane & 7;
    const int aRow = (part & 1) * 8 + l8, aCol = (part >> 1) * 8;
    const int bRow = (part >> 1) * 8 + l8, bCol = (part & 1) * 8;

    float acc[4][4][4] = {};

    for (int c = 0; c < NCHK; c++) {
        const int s = c % 3;
        asm volatile("cp.async.wait_group 2;");
        __syncthreads();

        const uint32_t sb = smb + s * STG;
        #pragma unroll
        for (int kk = 0; kk < 2; kk++) {
            uint32_t ah[16], al[16], bh[8], bl[8];
            #pragma unroll
            for (int mi = 0; mi < 4; mi++) {
                uint32_t off = (uint32_t)((wm * 64 + mi * 16 + aRow) * 80
                                          + (kk * 16 + aCol) * 2);
                ldm4(&ah[mi * 4], sb + off);
                ldm4(&al[mi * 4], sb + MAT + off);
            }
            #pragma unroll
            for (int f = 0; f < 2; f++) {
                uint32_t off = (uint32_t)((wn * 32 + f * 16 + bRow) * 80
                                          + (kk * 16 + bCol) * 2);
                ldm4(&bh[f * 4], sb + 2 * MAT + off);
                ldm4(&bl[f * 4], sb + 3 * MAT + off);
            }
            #pragma unroll
            for (int mi = 0; mi < 4; mi++)
                #pragma unroll
                for (int ni = 0; ni < 4; ni++) {
                    uint32_t* bph = &bh[(ni >> 1) * 4 + (ni & 1) * 2];
                    uint32_t* bpl = &bl[(ni >> 1) * 4 + (ni & 1) * 2];
                    mma16816(acc[mi][ni], &ah[mi * 4], bph);
                    mma16816(acc[mi][ni], &ah[mi * 4], bpl);
                    mma16816(acc[mi][ni], &al[mi * 4], bph);
                }
        }
        __syncthreads();
        if (c + 3 < NCHK) issue(c + 3, s);
    }

    const int g = lane >> 2, cc = (lane & 3) * 2;
    #pragma unroll
    for (int mi = 0; mi < 4; mi++) {
        const int r0 = by * 128 + wm * 64 + mi * 16 + g;
        #pragma unroll
        for (int ni = 0; ni < 4; ni++) {
            const int col = bx * 128 + wn * 32 + ni * 8 + cc;
            const float b0 = bias[col], b1 = bias[col + 1];
            float2 o0, o1;
            o0.x = acc[mi][ni][0] + b0; o0.y = acc[mi][ni][1] + b1;
            o1.x = acc[mi][ni][2] + b0; o1.y = acc[mi][ni][3] + b1;
            *(float2*)(C + (size_t)r0 * DM + col)       = o0;
            *(float2*)(C + (size_t)(r0 + 8) * DM + col) = o1;
        }
    }
}

// ------------------- FAVOR+ feature kernel (q or k) -------------------------
// Writes bf16 features. IS_Q also computes denom from the ROUNDED values.
#define FEAT_SMEM ((64*256 + 8*4*64) * 4)

template <bool IS_Q>
__global__ __launch_bounds__(256)
void k_feat(const float* __restrict__ X, const float* __restrict__ proj,
            __nv_bfloat16* __restrict__ out, const float* __restrict__ k1,
            float* __restrict__ den)
{
    float* sm = dynsm;
    float* projT = sm;
    float* sq    = sm + 64 * 256;
    const int tid = threadIdx.x;
    const int w = tid >> 5, l = tid & 31;

    for (int i = tid; i < 64 * 256; i += 256) {
        int k = i >> 8, r = i & 255;
        projT[i] = CNORM * proj[r * 64 + k];
    }
    __syncthreads();

    const float4* pT = (const float4*)projT;
    float* sqw = sq + w * 4 * 64;
    float wmax = -3.0e38f;
    const int jrow = l >> 3;
    const int off  = (l & 7) * 8;
    const int base = blockIdx.x * 512 + w * 64;

    for (int it = 0; it < 16; it++) {
        const int n0 = base + it * 4;
        const float* xp = X + (n0 + jrow) * 64 + off;
        float4 xa = *(const float4*)xp;
        float4 xb = *(const float4*)(xp + 4);
        float ss = xa.x*xa.x + xa.y*xa.y + xa.z*xa.z + xa.w*xa.w
                 + xb.x*xb.x + xb.y*xb.y + xb.z*xb.z + xb.w*xb.w;
        ss += __shfl_xor_sync(0xffffffffu, ss, 1);
        ss += __shfl_xor_sync(0xffffffffu, ss, 2);
        ss += __shfl_xor_sync(0xffffffffu, ss, 4);
        float diagl = 0.0625f * ss;
        float diag[4];
        #pragma unroll
        for (int j = 0; j < 4; j++)
            diag[j] = __shfl_sync(0xffffffffu, diagl, j * 8);

        __syncwarp();
        *(float4*)&sqw[jrow * 64 + off]     = xa;
        *(float4*)&sqw[jrow * 64 + off + 4] = xb;
        __syncwarp();

        float4 a0[4] = {}, a1[4] = {};
        #pragma unroll 2
        for (int k = 0; k < 64; k++) {
            float4 p0 = pT[k * 64 + l];
            float4 p1 = pT[k * 64 + 32 + l];
            #pragma unroll
            for (int j = 0; j < 4; j++) {
                float qk = sqw[j * 64 + k];
                a0[j].x = fmaf(qk, p0.x, a0[j].x);
                a0[j].y = fmaf(qk, p0.y, a0[j].y);
                a0[j].z = fmaf(qk, p0.z, a0[j].z);
                a0[j].w = fmaf(qk, p0.w, a0[j].w);
                a1[j].x = fmaf(qk, p1.x, a1[j].x);
                a1[j].y = fmaf(qk, p1.y, a1[j].y);
                a1[j].z = fmaf(qk, p1.z, a1[j].z);
                a1[j].w = fmaf(qk, p1.w, a1[j].w);
            }
        }
        #pragma unroll
        for (int j = 0; j < 4; j++) {
            const int n = n0 + j;
            __nv_bfloat16* op = out + n * 256 + 4 * l;
            float lm = fmaxf(fmaxf(fmaxf(a0[j].x, a0[j].y), fmaxf(a0[j].z, a0[j].w)),
                             fmaxf(fmaxf(a1[j].x, a1[j].y), fmaxf(a1[j].z, a1[j].w)));
            if (IS_Q) {
                #pragma unroll
                for (int o = 16; o > 0; o >>= 1)
                    lm = fmaxf(lm, __shfl_xor_sync(0xffffffffu, lm, o));
                const float sub = diag[j] + lm;
                float v[8];
                v[0] = rbf(RATIO * (fexp(a0[j].x - sub) + 1e-4f));
                v[1] = rbf(RATIO * (fexp(a0[j].y - sub) + 1e-4f));
                v[2] = rbf(RATIO * (fexp(a0[j].z - sub) + 1e-4f));
                v[3] = rbf(RATIO * (fexp(a0[j].w - sub) + 1e-4f));
                v[4] = rbf(RATIO * (fexp(a1[j].x - sub) + 1e-4f));
                v[5] = rbf(RATIO * (fexp(a1[j].y - sub) + 1e-4f));
                v[6] = rbf(RATIO * (fexp(a1[j].z - sub) + 1e-4f));
                v[7] = rbf(RATIO * (fexp(a1[j].w - sub) + 1e-4f));
                uint2 s0, s1;
                s0.x = pack2(v[0], v[1]); s0.y = pack2(v[2], v[3]);
                s1.x = pack2(v[4], v[5]); s1.y = pack2(v[6], v[7]);
                *(uint2*)op         = s0;
                *(uint2*)(op + 128) = s1;
                const int bh = ((n >> 16) << 4) | (n & 15);
                const float* kp = k1 + bh * 256 + 4 * l;
                float4 c0 = *(const float4*)kp;
                float4 c1 = *(const float4*)(kp + 128);
                float dp = v[0]*c0.x + v[1]*c0.y + v[2]*c0.z + v[3]*c0.w
                         + v[4]*c1.x + v[5]*c1.y + v[6]*c1.z + v[7]*c1.w;
                #pragma unroll
                for (int o = 16; o > 0; o >>= 1)
                    dp += __shfl_xor_sync(0xffffffffu, dp, o);
                if (l == 0) den[n] = dp;
            } else {
                wmax = fmaxf(wmax, lm);
                const float sub = diag[j];
                uint2 s0, s1;
                s0.x = pack2(fexp(a0[j].x - sub), fexp(a0[j].y - sub));
                s0.y = pack2(fexp(a0[j].z - sub), fexp(a0[j].w - sub));
                s1.x = pack2(fexp(a1[j].x - sub), fexp(a1[j].y - sub));
                s1.y = pack2(fexp(a1[j].z - sub), fexp(a1[j].w - sub));
                *(uint2*)op         = s0;
                *(uint2*)(op + 128) = s1;
            }
        }
    }
    if (!IS_Q) {
        #pragma unroll
        for (int o = 16; o > 0; o >>= 1)
            wmax = fmaxf(wmax, __shfl_xor_sync(0xffffffffu, wmax, o));
        __syncthreads();
        if (l == 0) sm[w] = wmax;
        __syncthreads();
        if (tid == 0) {
            float m = sm[0];
            #pragma unroll
            for (int i = 1; i < 8; i++) m = fmaxf(m, sm[i]);
            atomicMaxF(&g_kmax, m);
        }
    }
}

// --------- kv partials: per (bh, S-chunk) compute u^T @ v [256 x 64] --------
__global__ __launch_bounds__(256)
void k_kv()
{
    __shared__ float Us[16][256];
    __shared__ float Vs[16][64];
    const int bh = blockIdx.x, c = blockIdx.y;
    const int b = bh >> 4, h = bh & 15;
    const int tid = threadIdx.x;
    const int ls = tid >> 4, lr = (tid & 15) * 16;
    const int lv = (tid & 15) * 4;
    const int tr = (tid >> 3) * 8, tv = (tid & 7) * 8;
    const __nv_bfloat16* ub = g_u + ((size_t)(b * S_ + c * SCH) * H_ + h) * RR;
    const float* vb = g_v + (size_t)(b * S_ + c * SCH) * DM + h * DH;

    float acc[8][8] = {};
    float uacc = 0.f, vacc = 0.f;
    for (int s0 = 0; s0 < SCH; s0 += 16) {
        const __nv_bfloat16* up = ub + (size_t)(s0 + ls) * (H_ * RR) + lr;
        uint4 d0 = *(const uint4*)up;          // 8 bf16
        uint4 d1 = *(const uint4*)(up + 8);    // 8 bf16
        float2 f;
        f = u2f(d0.x); Us[ls][lr + 0]  = f.x; Us[ls][lr + 1]  = f.y;
        f = u2f(d0.y); Us[ls][lr + 2]  = f.x; Us[ls][lr + 3]  = f.y;
        f = u2f(d0.z); Us[ls][lr + 4]  = f.x; Us[ls][lr + 5]  = f.y;
        f = u2f(d0.w); Us[ls][lr + 6]  = f.x; Us[ls][lr + 7]  = f.y;
        f = u2f(d1.x); Us[ls][lr + 8]  = f.x; Us[ls][lr + 9]  = f.y;
        f = u2f(d1.y); Us[ls][lr + 10] = f.x; Us[ls][lr + 11] = f.y;
        f = u2f(d1.z); Us[ls][lr + 12] = f.x; Us[ls][lr + 13] = f.y;
        f = u2f(d1.w); Us[ls][lr + 14] = f.x; Us[ls][lr + 15] = f.y;
        *(float4*)&Vs[ls][lv] = *(const float4*)(vb + (size_t)(s0 + ls) * DM + lv);
        __syncthreads();
        #pragma unroll
        for (int s = 0; s < 16; s++) {
            float ua[8], va[8];
            *(float4*)&ua[0] = *(const float4*)&Us[s][tr];
            *(float4*)&ua[4] = *(const float4*)&Us[s][tr + 4];
            *(float4*)&va[0] = *(const float4*)&Vs[s][tv];
            *(float4*)&va[4] = *(const float4*)&Vs[s][tv + 4];
            #pragma unroll
            for (int i = 0; i < 8; i++)
                #pragma unroll
                for (int j = 0; j < 8; j++)
                    acc[i][j] = fmaf(ua[i], va[j], acc[i][j]);
            uacc += Us[s][tid];
            if (tid < 64) vacc += Vs[s][tid];
        }
        __syncthreads();
    }
    const int pb = c * BH + bh;
    float* kp = g_kvp + (size_t)pb * (RR * DH);
    #pragma unroll
    for (int i = 0; i < 8; i++) {
        *(float4*)&kp[(tr + i) * DH + tv]     = *(float4*)&acc[i][0];
        *(float4*)&kp[(tr + i) * DH + tv + 4] = *(float4*)&acc[i][4];
    }
    g_u1p[pb * RR + tid] = uacc;
    if (tid < 64) g_v1p[pb * DH + tid] = vacc;
}

__global__ void k_red()
{
    const int bh = blockIdx.x, t = threadIdx.x;
    const float a = RATIO * fexp(-g_kmax);
    float s = 0.f;
    #pragma unroll
    for (int c = 0; c < SPLIT; c++) s += g_u1p[(c * BH + bh) * RR + t];
    g_k1[bh * RR + t] = a * s + RATIO * 1e-4f * (float)S_;
    if (t < DH) {
        float vs = 0.f;
        #pragma unroll
        for (int c = 0; c < SPLIT; c++) vs += g_v1p[(c * BH + bh) * DH + t];
        g_v1[bh * DH + t] = vs;
    }
}

__global__ void k_kvred()
{
    const int bh = blockIdx.x, r = blockIdx.y, v = threadIdx.x;
    const float a = RATIO * fexp(-g_kmax);
    float s = 0.f;
    #pragma unroll
    for (int c = 0; c < SPLIT; c++)
        s += g_kvp[((size_t)(c * BH + bh) * RR + r) * DH + v];
    g_kvf[((size_t)bh * RR + r) * DH + v] = a * s + RATIO * 1e-4f * g_v1[bh * DH + v];
}

// ----- attention out: qhat[128,256] @ kvf[256,64], /denom, emit bf16 hi/lo --
__global__ __launch_bounds__(256)
void k_att()
{
    __shared__ float As[16][128];
    __shared__ float Bs[16][64];
    const int bh = blockIdx.x, sc = blockIdx.y;
    const int b = bh >> 4, h = bh & 15;
    const int tid = threadIdx.x;
    const int srow = tid >> 1, kcol = (tid & 1) * 8;
    const int krow = tid >> 4, vcol = (tid & 15) * 4;
    const int ts = (tid >> 3) * 4, tv = (tid & 7) * 8;
    const int s_base = sc * 128;
    const __nv_bfloat16* qb = g_qhat + ((size_t)(b * S_ + s_base) * H_ + h) * RR;
    const float* kvb = g_kvf + (size_t)bh * (RR * DH);

    float acc[4][8] = {};
    for (int k0 = 0; k0 < RR; k0 += 16) {
        const __nv_bfloat16* qp = qb + (size_t)srow * (H_ * RR) + k0 + kcol;
        uint4 d = *(const uint4*)qp;            // 8 bf16
        float2 f;
        f = u2f(d.x); As[kcol + 0][srow] = f.x; As[kcol + 1][srow] = f.y;
        f = u2f(d.y); As[kcol + 2][srow] = f.x; As[kcol + 3][srow] = f.y;
        f = u2f(d.z); As[kcol + 4][srow] = f.x; As[kcol + 5][srow] = f.y;
        f = u2f(d.w); As[kcol + 6][srow] = f.x; As[kcol + 7][srow] = f.y;
        *(float4*)&Bs[krow][vcol] = *(const float4*)(kvb + (k0 + krow) * DH + vcol);
        __syncthreads();
        #pragma unroll
        for (int k = 0; k < 16; k++) {
            float a4[4], b8[8];
            a4[0] = As[k][ts + 0];
            a4[1] = As[k][ts + 1];
            a4[2] = As[k][ts + 2];
            a4[3] = As[k][ts + 3];
            *(float4*)&b8[0] = *(const float4*)&Bs[k][tv];
            *(float4*)&b8[4] = *(const float4*)&Bs[k][tv + 4];
            #pragma unroll
            for (int i = 0; i < 4; i++)
                #pragma unroll
                for (int j = 0; j < 8; j++)
                    acc[i][j] = fmaf(a4[i], b8[j], acc[i][j]);
        }
        __syncthreads();
    }
    #pragma unroll
    for (int i = 0; i < 4; i++) {
        const int s = s_base + ts + i;
        const int n = (b * S_ + s) * H_ + h;
        const float inv = 1.0f / g_den[n];
        const size_t ob = (size_t)(b * S_ + s) * DM + h * DH + tv;
        float v[8], hi[8], lo[8];
        #pragma unroll
        for (int j = 0; j < 8; j++) v[j] = acc[i][j] * inv;
        #pragma unroll
        for (int j = 0; j < 8; j++) {
            hi[j] = rbf(v[j]);
            lo[j] = v[j] - hi[j];
        }
        uint4 ph, pl;
        ph.x = pack2(hi[0], hi[1]); ph.y = pack2(hi[2], hi[3]);
        ph.z = pack2(hi[4], hi[5]); ph.w = pack2(hi[6], hi[7]);
        pl.x = pack2(lo[0], lo[1]); pl.y = pack2(lo[2], lo[3]);
        pl.z = pack2(lo[4], lo[5]); pl.w = pack2(lo[6], lo[7]);
        *(uint4*)(g_ah + ob) = ph;
        *(uint4*)(g_al + ob) = pl;
    }
}

// ---------------------------------------------------------------------------
extern "C" void kernel_launch(void* const* d_in, const int* in_sizes, int n_in,
                              void* d_out, int out_size)
{
    const float* query = (const float*)d_in[0];
    const float* key   = (const float*)d_in[1];
    const float* value = (const float*)d_in[2];
    const float* Wq    = (const float*)d_in[3];
    const float* bq    = (const float*)d_in[4];
    const float* Wk    = (const float*)d_in[5];
    const float* bk    = (const float*)d_in[6];
    const float* Wv    = (const float*)d_in[7];
    const float* bv    = (const float*)d_in[8];
    const float* Wo    = (const float*)d_in[9];
    const float* bo    = (const float*)d_in[10];
    const float* proj  = (const float*)d_in[11];
    float* out = (float*)d_out;

    void *pq, *pk, *pv, *pqh, *pu, *pk1, *pden, *pah, *pal, *pwh, *pwl;
    cudaGetSymbolAddress(&pq,  g_q);
    cudaGetSymbolAddress(&pk,  g_k);
    cudaGetSymbolAddress(&pv,  g_v);
    cudaGetSymbolAddress(&pqh, g_qhat);
    cudaGetSymbolAddress(&pu,  g_u);
    cudaGetSymbolAddress(&pk1, g_k1);
    cudaGetSymbolAddress(&pden, g_den);
    cudaGetSymbolAddress(&pah, g_ah);
    cudaGetSymbolAddress(&pal, g_al);
    cudaGetSymbolAddress(&pwh, g_wh);
    cudaGetSymbolAddress(&pwl, g_wl);

    cudaFuncSetAttribute(k_feat<true>,  cudaFuncAttributeMaxDynamicSharedMemorySize, FEAT_SMEM);
    cudaFuncSetAttribute(k_feat<false>, cudaFuncAttributeMaxDynamicSharedMemorySize, FEAT_SMEM);
    cudaFuncSetAttribute(k_mm, cudaFuncAttributeMaxDynamicSharedMemorySize, MM_SMEM);

    __nv_bfloat16* ah = (__nv_bfloat16*)pah;
    __nv_bfloat16* al = (__nv_bfloat16*)pal;
    __nv_bfloat16* wh = (__nv_bfloat16*)pwh;
    __nv_bfloat16* wl = (__nv_bfloat16*)pwl;

    const int CVT_G = MROWS * DM / 4 / 256;     // 16384
    const dim3 WT_G(DM / 32, DM / 32);          // (32, 32)
    const dim3 WT_B(32, 8);
    const dim3 MM_G(DM / 128, MROWS / 128);     // (8, 128)

    k_init<<<1, 1>>>();

    // Q = query @ Wq + bq
    k_cvt_act<<<CVT_G, 256>>>((const float4*)query, (uint2*)ah, (uint2*)al);
    k_cvt_wt<<<WT_G, WT_B>>>(Wq, wh, wl);
    k_mm<<<MM_G, 256, MM_SMEM>>>(ah, al, wh, wl, bq, (float*)pq);
    // K = key @ Wk + bk
    k_cvt_act<<<CVT_G, 256>>>((const float4*)key, (uint2*)ah, (uint2*)al);
    k_cvt_wt<<<WT_G, WT_B>>>(Wk, wh, wl);
    k_mm<<<MM_G, 256, MM_SMEM>>>(ah, al, wh, wl, bk, (float*)pk);
    // V = value @ Wv + bv
    k_cvt_act<<<CVT_G, 256>>>((const float4*)value, (uint2*)ah, (uint2*)al);
    k_cvt_wt<<<WT_G, WT_B>>>(Wv, wh, wl);
    k_mm<<<MM_G, 256, MM_SMEM>>>(ah, al, wh, wl, bv, (float*)pv);

    // key feature path first (global max + k1 before fused q/denom kernel)
    k_feat<false><<<NROWS / 512, 256, FEAT_SMEM>>>((const float*)pk, proj,
                                                   (__nv_bfloat16*)pu, nullptr, nullptr);
    k_kv<<<dim3(BH, SPLIT), 256>>>();
    k_red<<<BH, 256>>>();
    k_kvred<<<dim3(BH, RR), DH>>>();

    k_feat<true><<<NROWS / 512, 256, FEAT_SMEM>>>((const float*)pq, proj,
                                                  (__nv_bfloat16*)pqh, (const float*)pk1,
                                                  (float*)pden);
    k_att<<<dim3(BH, S_ / 128), 256>>>();   // writes split-bf16 into g_ah/g_al

    // out = att @ Wo + bo
    k_cvt_wt<<<WT_G, WT_B>>>(Wo, wh, wl);
    k_mm<<<MM_G, 256, MM_SMEM>>>(ah, al, wh, wl, bo, out);
}

// round 13
// speedup vs baseline: 1.1807x; 1.0807x over previous
#include <cuda_runtime.h>
#include <cuda_bf16.h>
#include <cstdint>

// ---------------------------------------------------------------------------
// Performer attention. B=4, S=4096, Dm=1024, H=16, Dh=64, R=256
// Big GEMMs + FAVOR+ feature GEMMs on mma.sync HMMA (split-bf16, fp32 accum).
// ---------------------------------------------------------------------------

#define B_    4
#define S_    4096
#define DM    1024
#define H_    16
#define DH    64
#define RR    256
#define MROWS (B_*S_)        // 16384
#define NROWS (B_*S_*H_)     // 262144
#define BH    (B_*H_)        // 64
#define SPLIT 8
#define SCH   (S_/SPLIT)     // 512

#define RATIO 0.0625f                 // 1/sqrt(R)
#define CNORM 0.35355339059327373f    // Dh^{-1/4}

// ------------------------------ scratch ------------------------------------
__device__ float g_v[MROWS*DM];
__device__ __nv_bfloat16 g_qh[MROWS*DM];     // Q projection split-bf16
__device__ __nv_bfloat16 g_ql[MROWS*DM];
__device__ __nv_bfloat16 g_kh[MROWS*DM];     // K projection split-bf16
__device__ __nv_bfloat16 g_kl[MROWS*DM];
__device__ __nv_bfloat16 g_qhat[NROWS*RR];   // bf16 q features
__device__ __nv_bfloat16 g_u[NROWS*RR];      // bf16 exp(dh - diag) for keys
__device__ __nv_bfloat16 g_ph[RR*DH];        // CNORM*proj split-bf16
__device__ __nv_bfloat16 g_pl[RR*DH];
__device__ float g_den[NROWS];
__device__ float g_kvp[SPLIT*BH*RR*DH];
__device__ float g_kvf[BH*RR*DH];
__device__ float g_u1p[SPLIT*BH*RR];
__device__ float g_v1p[SPLIT*BH*DH];
__device__ float g_k1[BH*RR];
__device__ float g_v1[BH*DH];
__device__ float g_kmax;
// bf16 split activation/weight buffers (reused across the 4 big GEMMs)
__device__ __nv_bfloat16 g_ah[MROWS*DM];
__device__ __nv_bfloat16 g_al[MROWS*DM];
__device__ __nv_bfloat16 g_wh[DM*DM];
__device__ __nv_bfloat16 g_wl[DM*DM];

extern __shared__ float dynsm[];

// ------------------------- FMA-pipe exp (no MUFU) --------------------------
__device__ __forceinline__ float fexp(float x)
{
    x = fminf(fmaxf(x, -87.0f), 87.0f);
    float z = x * 1.4426950408889634f;
    float t = z + 12582912.0f;
    int   n = __float_as_int(t) - 0x4B400000;
    float f = z - (t - 12582912.0f);
    float p = 1.3333558e-3f;
    p = fmaf(p, f, 9.6181291e-3f);
    p = fmaf(p, f, 5.5504109e-2f);
    p = fmaf(p, f, 2.4022651e-1f);
    p = fmaf(p, f, 6.9314718e-1f);
    p = fmaf(p, f, 1.0f);
    return p * __int_as_float((n + 127) << 23);
}

__device__ __forceinline__ void atomicMaxF(float* addr, float v)
{
    int* ia = (int*)addr;
    int old = *ia;
    while (__int_as_float(old) < v) {
        int assumed = old;
        old = atomicCAS(ia, assumed, __float_as_int(v));
        if (old == assumed) break;
    }
}

__global__ void k_init() { g_kmax = -3.0e38f; }

// ----------------------- PTX helpers (compute_103-safe) ---------------------
__device__ __forceinline__ uint32_t s2u(const void* p)
{
    uint32_t a;
    asm("{ .reg .u64 t; cvta.to.shared.u64 t, %1; cvt.u32.u64 %0, t; }"
        : "=r"(a) : "l"(p));
    return a;
}
__device__ __forceinline__ void cp16(uint32_t s, const void* g)
{
    asm volatile("cp.async.cg.shared.global [%0], [%1], 16;"
                 :: "r"(s), "l"(g));
}
__device__ __forceinline__ void ldm4(uint32_t* r, uint32_t addr)
{
    asm volatile("ldmatrix.sync.aligned.m8n8.x4.shared.b16 {%0,%1,%2,%3}, [%4];"
                 : "=r"(r[0]), "=r"(r[1]), "=r"(r[2]), "=r"(r[3]) : "r"(addr));
}
__device__ __forceinline__ void mma16816(float* c, const uint32_t* a,
                                         const uint32_t* b)
{
    asm volatile("mma.sync.aligned.m16n8k16.row.col.f32.bf16.bf16.f32 "
                 "{%0,%1,%2,%3}, {%4,%5,%6,%7}, {%8,%9}, {%0,%1,%2,%3};"
                 : "+f"(c[0]), "+f"(c[1]), "+f"(c[2]), "+f"(c[3])
                 : "r"(a[0]), "r"(a[1]), "r"(a[2]), "r"(a[3]),
                   "r"(b[0]), "r"(b[1]));
}
__device__ __forceinline__ uint32_t pack2(float a, float b)
{
    return (uint32_t)__bfloat16_as_ushort(__float2bfloat16(a))
         | ((uint32_t)__bfloat16_as_ushort(__float2bfloat16(b)) << 16);
}
__device__ __forceinline__ float rbf(float x)
{
    return __bfloat162float(__float2bfloat16(x));
}
__device__ __forceinline__ float2 u2f(uint32_t u)
{
    __nv_bfloat162 h = *(__nv_bfloat162*)&u;
    return __bfloat1622float2(h);
}

// ------------------------ split-bf16 conversion -----------------------------
__global__ __launch_bounds__(256)
void k_cvt_act(const float4* __restrict__ X, uint2* __restrict__ Hh,
               uint2* __restrict__ Hl)
{
    const int i = blockIdx.x * 256 + threadIdx.x;
    float4 x = X[i];
    float hx = rbf(x.x), hy = rbf(x.y), hz = rbf(x.z), hw = rbf(x.w);
    uint2 h; h.x = pack2(hx, hy); h.y = pack2(hz, hw);
    uint2 l; l.x = pack2(x.x - hx, x.y - hy); l.y = pack2(x.z - hz, x.w - hw);
    Hh[i] = h; Hl[i] = l;
}

__global__ void k_cvt_wt(const float* __restrict__ W, __nv_bfloat16* __restrict__ Th,
                         __nv_bfloat16* __restrict__ Tl)
{
    __shared__ float t[32][33];
    const int n0 = blockIdx.x * 32, k0 = blockIdx.y * 32;
    const int tx = threadIdx.x, ty = threadIdx.y;
    #pragma unroll
    for (int j = 0; j < 32; j += 8)
        t[ty + j][tx] = W[(size_t)(k0 + ty + j) * DM + n0 + tx];
    __syncthreads();
    #pragma unroll
    for (int j = 0; j < 32; j += 8) {
        float v = t[tx][ty + j];
        __nv_bfloat16 h = __float2bfloat16(v);
        Th[(size_t)(n0 + ty + j) * DM + k0 + tx] = h;
        Tl[(size_t)(n0 + ty + j) * DM + k0 + tx] =
            __float2bfloat16(v - __bfloat162float(h));
    }
}

// proj [256][64] -> CNORM-scaled split bf16 (no transpose: already [N][K])
__global__ void k_cvt_proj(const float* __restrict__ P)
{
    const int i = blockIdx.x * 256 + threadIdx.x;   // 64 blocks
    if (i < RR * DH) {
        float v = CNORM * P[i];
        float h = rbf(v);
        g_ph[i] = __float2bfloat16(h);
        g_pl[i] = __float2bfloat16(v - h);
    }
}

// -------------- HMMA GEMM: C[16384,1024] = A @ B^T (+bias) ------------------
// R6 geometry: 128x128 tile, 256 thr, K-chunk 32, 3-stage cp.async.
// OUT=0: fp32 C. OUT=1: split-bf16 (Ch, Cl).
#define MCHK  32
#define NCHK  (DM / MCHK)
#define MAT   (128 * 80)
#define STG   (4 * MAT)
#define MM_SMEM (3 * STG)          // 122880 B

template <int OUT>
__global__ __launch_bounds__(256)
void k_mm(const __nv_bfloat16* __restrict__ Ah, const __nv_bfloat16* __restrict__ Al,
          const __nv_bfloat16* __restrict__ Bh, const __nv_bfloat16* __restrict__ Bl,
          const float* __restrict__ bias, float* __restrict__ C,
          __nv_bfloat16* __restrict__ Ch, __nv_bfloat16* __restrict__ Cl)
{
    const uint32_t smb = s2u(dynsm);
    const int tid = threadIdx.x, wid = tid >> 5, lane = tid & 31;
    const int bx = blockIdx.x, by = blockIdx.y;
    const int wm = wid & 1, wn = wid >> 1;

    const __nv_bfloat16* gbase[4];
    gbase[0] = Ah + (size_t)(by * 128) * DM;
    gbase[1] = Al + (size_t)(by * 128) * DM;
    gbase[2] = Bh + (size_t)(bx * 128) * DM;
    gbase[3] = Bl + (size_t)(bx * 128) * DM;

    int lmat[8], lrow[8], lq[8];
    #pragma unroll
    for (int t = 0; t < 8; t++) {
        int idx = tid + t * 256;
        lmat[t] = idx >> 9;
        lrow[t] = (idx >> 2) & 127;
        lq[t]   = idx & 3;
    }

    auto issue = [&](int c, int s) {
        const int k0 = c * MCHK;
        #pragma unroll
        for (int t = 0; t < 8; t++) {
            const __nv_bfloat16* gp = gbase[lmat[t]] + (size_t)lrow[t] * DM
                                      + k0 + lq[t] * 8;
            uint32_t sa = smb + s * STG + lmat[t] * MAT + lrow[t] * 80 + lq[t] * 16;
            cp16(sa, gp);
        }
        asm volatile("cp.async.commit_group;");
    };

    issue(0, 0);
    issue(1, 1);
    issue(2, 2);

    const int part = lane >> 3, l8 = lane & 7;
    const int aRow = (part & 1) * 8 + l8, aCol = (part >> 1) * 8;
    const int bRow = (part >> 1) * 8 + l8, bCol = (part & 1) * 8;

    float acc[4][4][4] = {};

    for (int c = 0; c < NCHK; c++) {
        const int s = c % 3;
        asm volatile("cp.async.wait_group 2;");
        __syncthreads();

        const uint32_t sb = smb + s * STG;
        #pragma unroll
        for (int kk = 0; kk < 2; kk++) {
            uint32_t ah[16], al[16], bh[8], bl[8];
            #pragma unroll
            for (int mi = 0; mi < 4; mi++) {
                uint32_t off = (uint32_t)((wm * 64 + mi * 16 + aRow) * 80
                                          + (kk * 16 + aCol) * 2);
                ldm4(&ah[mi * 4], sb + off);
                ldm4(&al[mi * 4], sb + MAT + off);
            }
            #pragma unroll
            for (int f = 0; f < 2; f++) {
                uint32_t off = (uint32_t)((wn * 32 + f * 16 + bRow) * 80
                                          + (kk * 16 + bCol) * 2);
                ldm4(&bh[f * 4], sb + 2 * MAT + off);
                ldm4(&bl[f * 4], sb + 3 * MAT + off);
            }
            #pragma unroll
            for (int mi = 0; mi < 4; mi++)
                #pragma unroll
                for (int ni = 0; ni < 4; ni++) {
                    uint32_t* bph = &bh[(ni >> 1) * 4 + (ni & 1) * 2];
                    uint32_t* bpl = &bl[(ni >> 1) * 4 + (ni & 1) * 2];
                    mma16816(acc[mi][ni], &ah[mi * 4], bph);
                    mma16816(acc[mi][ni], &ah[mi * 4], bpl);
                    mma16816(acc[mi][ni], &al[mi * 4], bph);
                }
        }
        __syncthreads();
        if (c + 3 < NCHK) issue(c + 3, s);
    }

    const int g = lane >> 2, cc = (lane & 3) * 2;
    #pragma unroll
    for (int mi = 0; mi < 4; mi++) {
        const int r0 = by * 128 + wm * 64 + mi * 16 + g;
        #pragma unroll
        for (int ni = 0; ni < 4; ni++) {
            const int col = bx * 128 + wn * 32 + ni * 8 + cc;
            const float b0 = bias[col], b1 = bias[col + 1];
            float v0 = acc[mi][ni][0] + b0, v1 = acc[mi][ni][1] + b1;
            float v2 = acc[mi][ni][2] + b0, v3 = acc[mi][ni][3] + b1;
            if (OUT == 0) {
                *(float2*)(C + (size_t)r0 * DM + col)       = make_float2(v0, v1);
                *(float2*)(C + (size_t)(r0 + 8) * DM + col) = make_float2(v2, v3);
            } else {
                float h0 = rbf(v0), h1 = rbf(v1), h2 = rbf(v2), h3 = rbf(v3);
                *(uint32_t*)(Ch + (size_t)r0 * DM + col)       = pack2(h0, h1);
                *(uint32_t*)(Cl + (size_t)r0 * DM + col)       = pack2(v0 - h0, v1 - h1);
                *(uint32_t*)(Ch + (size_t)(r0 + 8) * DM + col) = pack2(h2, h3);
                *(uint32_t*)(Cl + (size_t)(r0 + 8) * DM + col) = pack2(v2 - h2, v3 - h3);
            }
        }
    }
}

// ----------------- FAVOR+ feature kernel on HMMA ----------------------------
// dh[128 rows][256 r] = X[128][64] @ (CNORM*proj)^T, split-bf16 3-term.
// IS_Q: qhat = RATIO*(exp(dh-diag-rowmax)+1e-4) bf16; den = qhat . k1[bh].
// !IS_Q: u = exp(dh-diag) bf16; global atomic max of dh.
#define F_AH 0
#define F_AL 18432
#define F_BH 36864
#define F_BL 73728
#define F_DG 110592
#define F_K1 111104
#define F_RD 127488
#define FEATM_SMEM 127552

template <bool IS_Q>
__global__ __launch_bounds__(256)
void k_featm(const __nv_bfloat16* __restrict__ Xh, const __nv_bfloat16* __restrict__ Xl,
             __nv_bfloat16* __restrict__ out, const float* __restrict__ k1,
             float* __restrict__ den)
{
    char* smc = (char*)dynsm;
    const uint32_t smb = s2u(smc);
    const int tid = threadIdx.x, w = tid >> 5, lane = tid & 31;
    const int n0 = blockIdx.x * 128;

    // ---- load A (128 rows x 64 bf16, hi/lo), stride 144B ----
    {
        const int r = tid >> 1, hf = tid & 1;
        const uint4* sh = (const uint4*)(Xh + (size_t)(n0 + r) * 64 + hf * 32);
        const uint4* sl = (const uint4*)(Xl + (size_t)(n0 + r) * 64 + hf * 32);
        char* dh_ = smc + F_AH + r * 144 + hf * 64;
        char* dl_ = smc + F_AL + r * 144 + hf * 64;
        #pragma unroll
        for (int i = 0; i < 4; i++) {
            *(uint4*)(dh_ + i * 16) = sh[i];
            *(uint4*)(dl_ + i * 16) = sl[i];
        }
    }
    // ---- load B (proj, 256 rows x 64 bf16, hi/lo) ----
    {
        const uint4* sh = (const uint4*)(g_ph + tid * 64);
        const uint4* sl = (const uint4*)(g_pl + tid * 64);
        char* dh_ = smc + F_BH + tid * 144;
        char* dl_ = smc + F_BL + tid * 144;
        #pragma unroll
        for (int i = 0; i < 8; i++) {
            *(uint4*)(dh_ + i * 16) = sh[i];
            *(uint4*)(dl_ + i * 16) = sl[i];
        }
    }
    // ---- k1 slice for this batch (IS_Q) ----
    if (IS_Q) {
        const int b = n0 >> 16;
        const float4* src = (const float4*)(k1 + b * 4096);
        float4* dst = (float4*)(smc + F_K1);
        #pragma unroll
        for (int j = 0; j < 4; j++)
            dst[tid * 4 + j] = src[tid * 4 + j];
    }
    __syncthreads();

    // ---- diag[r] = 0.0625 * |x|^2 (from hi+lo reconstruction) ----
    if (tid < 128) {
        const __nv_bfloat162* ph = (const __nv_bfloat162*)(smc + F_AH + tid * 144);
        const __nv_bfloat162* pl = (const __nv_bfloat162*)(smc + F_AL + tid * 144);
        float ss = 0.f;
        #pragma unroll
        for (int i = 0; i < 32; i++) {
            float2 h = __bfloat1622float2(ph[i]);
            float2 l = __bfloat1622float2(pl[i]);
            float x0 = h.x + l.x, x1 = h.y + l.y;
            ss = fmaf(x0, x0, ss);
            ss = fmaf(x1, x1, ss);
        }
        ((float*)(smc + F_DG))[tid] = 0.0625f * ss;
    }
    __syncthreads();

    // ---- MMA: warp w -> rows 16w..16w+15, all 256 cols ----
    const int part = lane >> 3, l8 = lane & 7;
    const int aRow = (part & 1) * 8 + l8, aCol = (part >> 1) * 8;
    const int bRow = (part >> 1) * 8 + l8, bCol = (part & 1) * 8;

    float acc[32][4];
    #pragma unroll
    for (int i = 0; i < 32; i++)
        #pragma unroll
        for (int j = 0; j < 4; j++) acc[i][j] = 0.f;

    #pragma unroll
    for (int ks = 0; ks < 4; ks++) {
        uint32_t ah[4], al[4];
        const uint32_t aoff = (uint32_t)((16 * w + aRow) * 144 + (ks * 16 + aCol) * 2);
        ldm4(ah, smb + F_AH + aoff);
        ldm4(al, smb + F_AL + aoff);
        #pragma unroll
        for (int p = 0; p < 16; p++) {
            uint32_t bh[4], bl[4];
            const uint32_t boff = (uint32_t)((p * 16 + bRow) * 144 + (ks * 16 + bCol) * 2);
            ldm4(bh, smb + F_BH + boff);
            ldm4(bl, smb + F_BL + boff);
            mma16816(acc[2 * p],     ah, &bh[0]);
            mma16816(acc[2 * p],     ah, &bl[0]);
            mma16816(acc[2 * p],     al, &bh[0]);
            mma16816(acc[2 * p + 1], ah, &bh[2]);
            mma16816(acc[2 * p + 1], ah, &bl[2]);
            mma16816(acc[2 * p + 1], al, &bh[2]);
        }
    }

    // ---- epilogue ----
    const int g = lane >> 2, cc = (lane & 3) * 2;
    const int lr0 = 16 * w + g;                 // local rows lr0, lr0+8
    const float d0 = ((float*)(smc + F_DG))[lr0];
    const float d1 = ((float*)(smc + F_DG))[lr0 + 8];

    if (IS_Q) {
        float m0 = -3.0e38f, m1 = -3.0e38f;
        #pragma unroll
        for (int nf = 0; nf < 32; nf++) {
            m0 = fmaxf(m0, fmaxf(acc[nf][0], acc[nf][1]));
            m1 = fmaxf(m1, fmaxf(acc[nf][2], acc[nf][3]));
        }
        m0 = fmaxf(m0, __shfl_xor_sync(0xffffffffu, m0, 1));
        m0 = fmaxf(m0, __shfl_xor_sync(0xffffffffu, m0, 2));
        m1 = fmaxf(m1, __shfl_xor_sync(0xffffffffu, m1, 1));
        m1 = fmaxf(m1, __shfl_xor_sync(0xffffffffu, m1, 2));
        const float s0 = d0 + m0, s1 = d1 + m1;
        const int h0 = lr0 & 15, h1 = (lr0 + 8) & 15;
        const float* k1s = (const float*)(smc + F_K1);
        float dp0 = 0.f, dp1 = 0.f;
        #pragma unroll
        for (int nf = 0; nf < 32; nf++) {
            const int col = nf * 8 + cc;
            float v0 = rbf(RATIO * (fexp(acc[nf][0] - s0) + 1e-4f));
            float v1 = rbf(RATIO * (fexp(acc[nf][1] - s0) + 1e-4f));
            float v2 = rbf(RATIO * (fexp(acc[nf][2] - s1) + 1e-4f));
            float v3 = rbf(RATIO * (fexp(acc[nf][3] - s1) + 1e-4f));
            *(uint32_t*)(out + (size_t)(n0 + lr0) * 256 + col)     = pack2(v0, v1);
            *(uint32_t*)(out + (size_t)(n0 + lr0 + 8) * 256 + col) = pack2(v2, v3);
            dp0 = fmaf(v0, k1s[h0 * 256 + col], dp0);
            dp0 = fmaf(v1, k1s[h0 * 256 + col + 1], dp0);
            dp1 = fmaf(v2, k1s[h1 * 256 + col], dp1);
            dp1 = fmaf(v3, k1s[h1 * 256 + col + 1], dp1);
        }
        dp0 += __shfl_xor_sync(0xffffffffu, dp0, 1);
        dp0 += __shfl_xor_sync(0xffffffffu, dp0, 2);
        dp1 += __shfl_xor_sync(0xffffffffu, dp1, 1);
        dp1 += __shfl_xor_sync(0xffffffffu, dp1, 2);
        if ((lane & 3) == 0) {
            den[n0 + lr0]     = dp0;
            den[n0 + lr0 + 8] = dp1;
        }
    } else {
        float wmax = -3.0e38f;
        #pragma unroll
        for (int nf = 0; nf < 32; nf++) {
            const int col = nf * 8 + cc;
            wmax = fmaxf(wmax, fmaxf(fmaxf(acc[nf][0], acc[nf][1]),
                                     fmaxf(acc[nf][2], acc[nf][3])));
            float v0 = fexp(acc[nf][0] - d0);
            float v1 = fexp(acc[nf][1] - d0);
            float v2 = fexp(acc[nf][2] - d1);
            float v3 = fexp(acc[nf][3] - d1);
            *(uint32_t*)(out + (size_t)(n0 + lr0) * 256 + col)     = pack2(v0, v1);
            *(uint32_t*)(out + (size_t)(n0 + lr0 + 8) * 256 + col) = pack2(v2, v3);
        }
        #pragma unroll
        for (int o = 16; o > 0; o >>= 1)
            wmax = fmaxf(wmax, __shfl_xor_sync(0xffffffffu, wmax, o));
        float* red = (float*)(smc + F_RD);
        if (lane == 0) red[w] = wmax;
        __syncthreads();
        if (tid == 0) {
            float m = red[0];
            #pragma unroll
            for (int i = 1; i < 8; i++) m = fmaxf(m, red[i]);
            atomicMaxF(&g_kmax, m);
        }
    }
}

// --------- kv partials: per (bh, S-chunk) compute u^T @ v [256 x 64] --------
__global__ __launch_bounds__(256)
void k_kv()
{
    __shared__ float Us[16][256];
    __shared__ float Vs[16][64];
    const int bh = blockIdx.x, c = blockIdx.y;
    const int b = bh >> 4, h = bh & 15;
    const int tid = threadIdx.x;
    const int ls = tid >> 4, lr = (tid & 15) * 16;
    const int lv = (tid & 15) * 4;
    const int tr = (tid >> 3) * 8, tv = (tid & 7) * 8;
    const __nv_bfloat16* ub = g_u + ((size_t)(b * S_ + c * SCH) * H_ + h) * RR;
    const float* vb = g_v + (size_t)(b * S_ + c * SCH) * DM + h * DH;

    float acc[8][8] = {};
    float uacc = 0.f, vacc = 0.f;
    for (int s0 = 0; s0 < SCH; s0 += 16) {
        const __nv_bfloat16* up = ub + (size_t)(s0 + ls) * (H_ * RR) + lr;
        uint4 d0 = *(const uint4*)up;
        uint4 d1 = *(const uint4*)(up + 8);
        float2 f;
        f = u2f(d0.x); Us[ls][lr + 0]  = f.x; Us[ls][lr + 1]  = f.y;
        f = u2f(d0.y); Us[ls][lr + 2]  = f.x; Us[ls][lr + 3]  = f.y;
        f = u2f(d0.z); Us[ls][lr + 4]  = f.x; Us[ls][lr + 5]  = f.y;
        f = u2f(d0.w); Us[ls][lr + 6]  = f.x; Us[ls][lr + 7]  = f.y;
        f = u2f(d1.x); Us[ls][lr + 8]  = f.x; Us[ls][lr + 9]  = f.y;
        f = u2f(d1.y); Us[ls][lr + 10] = f.x; Us[ls][lr + 11] = f.y;
        f = u2f(d1.z); Us[ls][lr + 12] = f.x; Us[ls][lr + 13] = f.y;
        f = u2f(d1.w); Us[ls][lr + 14] = f.x; Us[ls][lr + 15] = f.y;
        *(float4*)&Vs[ls][lv] = *(const float4*)(vb + (size_t)(s0 + ls) * DM + lv);
        __syncthreads();
        #pragma unroll
        for (int s = 0; s < 16; s++) {
            float ua[8], va[8];
            *(float4*)&ua[0] = *(const float4*)&Us[s][tr];
            *(float4*)&ua[4] = *(const float4*)&Us[s][tr + 4];
            *(float4*)&va[0] = *(const float4*)&Vs[s][tv];
            *(float4*)&va[4] = *(const float4*)&Vs[s][tv + 4];
            #pragma unroll
            for (int i = 0; i < 8; i++)
                #pragma unroll
                for (int j = 0; j < 8; j++)
                    acc[i][j] = fmaf(ua[i], va[j], acc[i][j]);
            uacc += Us[s][tid];
            if (tid < 64) vacc += Vs[s][tid];
        }
        __syncthreads();
    }
    const int pb = c * BH + bh;
    float* kp = g_kvp + (size_t)pb * (RR * DH);
    #pragma unroll
    for (int i = 0; i < 8; i++) {
        *(float4*)&kp[(tr + i) * DH + tv]     = *(float4*)&acc[i][0];
        *(float4*)&kp[(tr + i) * DH + tv + 4] = *(float4*)&acc[i][4];
    }
    g_u1p[pb * RR + tid] = uacc;
    if (tid < 64) g_v1p[pb * DH + tid] = vacc;
}

__global__ void k_red()
{
    const int bh = blockIdx.x, t = threadIdx.x;
    const float a = RATIO * fexp(-g_kmax);
    float s = 0.f;
    #pragma unroll
    for (int c = 0; c < SPLIT; c++) s += g_u1p[(c * BH + bh) * RR + t];
    g_k1[bh * RR + t] = a * s + RATIO * 1e-4f * (float)S_;
    if (t < DH) {
        float vs = 0.f;
        #pragma unroll
        for (int c = 0; c < SPLIT; c++) vs += g_v1p[(c * BH + bh) * DH + t];
        g_v1[bh * DH + t] = vs;
    }
}

__global__ void k_kvred()
{
    const int bh = blockIdx.x, r = blockIdx.y, v = threadIdx.x;
    const float a = RATIO * fexp(-g_kmax);
    float s = 0.f;
    #pragma unroll
    for (int c = 0; c < SPLIT; c++)
        s += g_kvp[((size_t)(c * BH + bh) * RR + r) * DH + v];
    g_kvf[((size_t)bh * RR + r) * DH + v] = a * s + RATIO * 1e-4f * g_v1[bh * DH + v];
}

// ----- attention out: qhat[128,256] @ kvf[256,64], /denom, emit bf16 hi/lo --
__global__ __launch_bounds__(256)
void k_att()
{
    __shared__ float As[16][128];
    __shared__ float Bs[16][64];
    const int bh = blockIdx.x, sc = blockIdx.y;
    const int b = bh >> 4, h = bh & 15;
    const int tid = threadIdx.x;
    const int srow = tid >> 1, kcol = (tid & 1) * 8;
    const int krow = tid >> 4, vcol = (tid & 15) * 4;
    const int ts = (tid >> 3) * 4, tv = (tid & 7) * 8;
    const int s_base = sc * 128;
    const __nv_bfloat16* qb = g_qhat + ((size_t)(b * S_ + s_base) * H_ + h) * RR;
    const float* kvb = g_kvf + (size_t)bh * (RR * DH);

    float acc[4][8] = {};
    for (int k0 = 0; k0 < RR; k0 += 16) {
        const __nv_bfloat16* qp = qb + (size_t)srow * (H_ * RR) + k0 + kcol;
        uint4 d = *(const uint4*)qp;
        float2 f;
        f = u2f(d.x); As[kcol + 0][srow] = f.x; As[kcol + 1][srow] = f.y;
        f = u2f(d.y); As[kcol + 2][srow] = f.x; As[kcol + 3][srow] = f.y;
        f = u2f(d.z); As[kcol + 4][srow] = f.x; As[kcol + 5][srow] = f.y;
        f = u2f(d.w); As[kcol + 6][srow] = f.x; As[kcol + 7][srow] = f.y;
        *(float4*)&Bs[krow][vcol] = *(const float4*)(kvb + (k0 + krow) * DH + vcol);
        __syncthreads();
        #pragma unroll
        for (int k = 0; k < 16; k++) {
            float a4[4], b8[8];
            a4[0] = As[k][ts + 0];
            a4[1] = As[k][ts + 1];
            a4[2] = As[k][ts + 2];
            a4[3] = As[k][ts + 3];
            *(float4*)&b8[0] = *(const float4*)&Bs[k][tv];
            *(float4*)&b8[4] = *(const float4*)&Bs[k][tv + 4];
            #pragma unroll
            for (int i = 0; i < 4; i++)
                #pragma unroll
                for (int j = 0; j < 8; j++)
                    acc[i][j] = fmaf(a4[i], b8[j], acc[i][j]);
        }
        __syncthreads();
    }
    #pragma unroll
    for (int i = 0; i < 4; i++) {
        const int s = s_base + ts + i;
        const int n = (b * S_ + s) * H_ + h;
        const float inv = 1.0f / g_den[n];
        const size_t ob = (size_t)(b * S_ + s) * DM + h * DH + tv;
        float v[8], hi[8], lo[8];
        #pragma unroll
        for (int j = 0; j < 8; j++) v[j] = acc[i][j] * inv;
        #pragma unroll
        for (int j = 0; j < 8; j++) {
            hi[j] = rbf(v[j]);
            lo[j] = v[j] - hi[j];
        }
        uint4 ph, pl;
        ph.x = pack2(hi[0], hi[1]); ph.y = pack2(hi[2], hi[3]);
        ph.z = pack2(hi[4], hi[5]); ph.w = pack2(hi[6], hi[7]);
        pl.x = pack2(lo[0], lo[1]); pl.y = pack2(lo[2], lo[3]);
        pl.z = pack2(lo[4], lo[5]); pl.w = pack2(lo[6], lo[7]);
        *(uint4*)(g_ah + ob) = ph;
        *(uint4*)(g_al + ob) = pl;
    }
}

// ---------------------------------------------------------------------------
extern "C" void kernel_launch(void* const* d_in, const int* in_sizes, int n_in,
                              void* d_out, int out_size)
{
    const float* query = (const float*)d_in[0];
    const float* key   = (const float*)d_in[1];
    const float* value = (const float*)d_in[2];
    const float* Wq    = (const float*)d_in[3];
    const float* bq    = (const float*)d_in[4];
    const float* Wk    = (const float*)d_in[5];
    const float* bk    = (const float*)d_in[6];
    const float* Wv    = (const float*)d_in[7];
    const float* bv    = (const float*)d_in[8];
    const float* Wo    = (const float*)d_in[9];
    const float* bo    = (const float*)d_in[10];
    const float* proj  = (const float*)d_in[11];
    float* out = (float*)d_out;

    void *pv, *pqh, *pql, *pkh, *pkl, *pqf, *pu, *pk1, *pden, *pah, *pal, *pwh, *pwl;
    cudaGetSymbolAddress(&pv,  g_v);
    cudaGetSymbolAddress(&pqh, g_qh);
    cudaGetSymbolAddress(&pql, g_ql);
    cudaGetSymbolAddress(&pkh, g_kh);
    cudaGetSymbolAddress(&pkl, g_kl);
    cudaGetSymbolAddress(&pqf, g_qhat);
    cudaGetSymbolAddress(&pu,  g_u);
    cudaGetSymbolAddress(&pk1, g_k1);
    cudaGetSymbolAddress(&pden, g_den);
    cudaGetSymbolAddress(&pah, g_ah);
    cudaGetSymbolAddress(&pal, g_al);
    cudaGetSymbolAddress(&pwh, g_wh);
    cudaGetSymbolAddress(&pwl, g_wl);

    cudaFuncSetAttribute(k_mm<0>, cudaFuncAttributeMaxDynamicSharedMemorySize, MM_SMEM);
    cudaFuncSetAttribute(k_mm<1>, cudaFuncAttributeMaxDynamicSharedMemorySize, MM_SMEM);
    cudaFuncSetAttribute(k_featm<true>,  cudaFuncAttributeMaxDynamicSharedMemorySize, FEATM_SMEM);
    cudaFuncSetAttribute(k_featm<false>, cudaFuncAttributeMaxDynamicSharedMemorySize, FEATM_SMEM);

    __nv_bfloat16* ah = (__nv_bfloat16*)pah;
    __nv_bfloat16* al = (__nv_bfloat16*)pal;
    __nv_bfloat16* wh = (__nv_bfloat16*)pwh;
    __nv_bfloat16* wl = (__nv_bfloat16*)pwl;

    const int CVT_G = MROWS * DM / 4 / 256;     // 16384
    const dim3 WT_G(DM / 32, DM / 32);
    const dim3 WT_B(32, 8);
    const dim3 MM_G(DM / 128, MROWS / 128);     // (8, 128)

    k_init<<<1, 1>>>();
    k_cvt_proj<<<64, 256>>>(proj);

    // Q = query @ Wq + bq  -> split bf16
    k_cvt_act<<<CVT_G, 256>>>((const float4*)query, (uint2*)ah, (uint2*)al);
    k_cvt_wt<<<WT_G, WT_B>>>(Wq, wh, wl);
    k_mm<1><<<MM_G, 256, MM_SMEM>>>(ah, al, wh, wl, bq, nullptr,
                                    (__nv_bfloat16*)pqh, (__nv_bfloat16*)pql);
    // K = key @ Wk + bk  -> split bf16
    k_cvt_act<<<CVT_G, 256>>>((const float4*)key, (uint2*)ah, (uint2*)al);
    k_cvt_wt<<<WT_G, WT_B>>>(Wk, wh, wl);
    k_mm<1><<<MM_G, 256, MM_SMEM>>>(ah, al, wh, wl, bk, nullptr,
                                    (__nv_bfloat16*)pkh, (__nv_bfloat16*)pkl);
    // V = value @ Wv + bv -> fp32
    k_cvt_act<<<CVT_G, 256>>>((const float4*)value, (uint2*)ah, (uint2*)al);
    k_cvt_wt<<<WT_G, WT_B>>>(Wv, wh, wl);
    k_mm<0><<<MM_G, 256, MM_SMEM>>>(ah, al, wh, wl, bv, (float*)pv, nullptr, nullptr);

    // key feature path first (global max + k1 before fused q/denom kernel)
    k_featm<false><<<NROWS / 128, 256, FEATM_SMEM>>>(
        (const __nv_bfloat16*)pkh, (const __nv_bfloat16*)pkl,
        (__nv_bfloat16*)pu, nullptr, nullptr);
    k_kv<<<dim3(BH, SPLIT), 256>>>();
    k_red<<<BH, 256>>>();
    k_kvred<<<dim3(BH, RR), DH>>>();

    k_featm<true><<<NROWS / 128, 256, FEATM_SMEM>>>(
        (const __nv_bfloat16*)pqh, (const __nv_bfloat16*)pql,
        (__nv_bfloat16*)pqf, (const float*)pk1, (float*)pden);
    k_att<<<dim3(BH, S_ / 128), 256>>>();

    // out = att @ Wo + bo
    k_cvt_wt<<<WT_G, WT_B>>>(Wo, wh, wl);
    k_mm<0><<<MM_G, 256, MM_SMEM>>>(ah, al, wh, wl, bo, out, nullptr, nullptr);
}

// round 15
// speedup vs baseline: 1.3970x; 1.1832x over previous
#include <cuda_runtime.h>
#include <cuda_bf16.h>
#include <cstdint>

// ---------------------------------------------------------------------------
// Performer attention. B=4, S=4096, Dm=1024, H=16, Dh=64, R=256
// All GEMM work (projections, features, kv, attention) on mma.sync HMMA.
// ---------------------------------------------------------------------------

#define B_    4
#define S_    4096
#define DM    1024
#define H_    16
#define DH    64
#define RR    256
#define MROWS (B_*S_)        // 16384
#define NROWS (B_*S_*H_)     // 262144
#define BH    (B_*H_)        // 64
#define SPLIT 8
#define SCH   (S_/SPLIT)     // 512

#define RATIO 0.0625f
#define CNORM 0.35355339059327373f

// ------------------------------ scratch ------------------------------------
__device__ __nv_bfloat16 g_vh[MROWS*DM];     // V projection split-bf16
__device__ __nv_bfloat16 g_vl[MROWS*DM];
__device__ __nv_bfloat16 g_qh[MROWS*DM];     // Q projection split-bf16
__device__ __nv_bfloat16 g_ql[MROWS*DM];
__device__ __nv_bfloat16 g_kh[MROWS*DM];     // K projection split-bf16
__device__ __nv_bfloat16 g_kl[MROWS*DM];
__device__ __nv_bfloat16 g_qhat[NROWS*RR];   // bf16 q features
__device__ __nv_bfloat16 g_u[NROWS*RR];      // bf16 exp(dh - diag)
__device__ __nv_bfloat16 g_ph[RR*DH];        // CNORM*proj split-bf16
__device__ __nv_bfloat16 g_pl[RR*DH];
__device__ __nv_bfloat16 g_kvfh[BH*DH*RR];   // kv final, TRANSPOSED [bh][v][r]
__device__ __nv_bfloat16 g_kvfl[BH*DH*RR];
__device__ float g_den[NROWS];
__device__ float g_kvp[SPLIT*BH*RR*DH];
__device__ float g_u1p[SPLIT*BH*RR];
__device__ float g_v1p[SPLIT*BH*DH];
__device__ float g_k1[BH*RR];
__device__ float g_v1[BH*DH];
__device__ float g_kmax;
__device__ __nv_bfloat16 g_ah[MROWS*DM];
__device__ __nv_bfloat16 g_al[MROWS*DM];
__device__ __nv_bfloat16 g_wh[DM*DM];
__device__ __nv_bfloat16 g_wl[DM*DM];

extern __shared__ float dynsm[];

// ------------------------- FMA-pipe exp (no MUFU) --------------------------
__device__ __forceinline__ float fexp(float x)
{
    x = fminf(fmaxf(x, -87.0f), 87.0f);
    float z = x * 1.4426950408889634f;
    float t = z + 12582912.0f;
    int   n = __float_as_int(t) - 0x4B400000;
    float f = z - (t - 12582912.0f);
    float p = 1.3333558e-3f;
    p = fmaf(p, f, 9.6181291e-3f);
    p = fmaf(p, f, 5.5504109e-2f);
    p = fmaf(p, f, 2.4022651e-1f);
    p = fmaf(p, f, 6.9314718e-1f);
    p = fmaf(p, f, 1.0f);
    return p * __int_as_float((n + 127) << 23);
}

__device__ __forceinline__ void atomicMaxF(float* addr, float v)
{
    int* ia = (int*)addr;
    int old = *ia;
    while (__int_as_float(old) < v) {
        int assumed = old;
        old = atomicCAS(ia, assumed, __float_as_int(v));
        if (old == assumed) break;
    }
}

__global__ void k_init() { g_kmax = -3.0e38f; }

// ----------------------- PTX helpers ---------------------------------------
__device__ __forceinline__ uint32_t s2u(const void* p)
{
    uint32_t a;
    asm("{ .reg .u64 t; cvta.to.shared.u64 t, %1; cvt.u32.u64 %0, t; }"
        : "=r"(a) : "l"(p));
    return a;
}
__device__ __forceinline__ void cp16(uint32_t s, const void* g)
{
    asm volatile("cp.async.cg.shared.global [%0], [%1], 16;"
                 :: "r"(s), "l"(g));
}
__device__ __forceinline__ void ldm4(uint32_t* r, uint32_t addr)
{
    asm volatile("ldmatrix.sync.aligned.m8n8.x4.shared.b16 {%0,%1,%2,%3}, [%4];"
                 : "=r"(r[0]), "=r"(r[1]), "=r"(r[2]), "=r"(r[3]) : "r"(addr));
}
__device__ __forceinline__ void ldm4t(uint32_t* r, uint32_t addr)
{
    asm volatile("ldmatrix.sync.aligned.m8n8.x4.trans.shared.b16 {%0,%1,%2,%3}, [%4];"
                 : "=r"(r[0]), "=r"(r[1]), "=r"(r[2]), "=r"(r[3]) : "r"(addr));
}
__device__ __forceinline__ void mma16816(float* c, const uint32_t* a,
                                         const uint32_t* b)
{
    asm volatile("mma.sync.aligned.m16n8k16.row.col.f32.bf16.bf16.f32 "
                 "{%0,%1,%2,%3}, {%4,%5,%6,%7}, {%8,%9}, {%0,%1,%2,%3};"
                 : "+f"(c[0]), "+f"(c[1]), "+f"(c[2]), "+f"(c[3])
                 : "r"(a[0]), "r"(a[1]), "r"(a[2]), "r"(a[3]),
                   "r"(b[0]), "r"(b[1]));
}
__device__ __forceinline__ uint32_t pack2(float a, float b)
{
    return (uint32_t)__bfloat16_as_ushort(__float2bfloat16(a))
         | ((uint32_t)__bfloat16_as_ushort(__float2bfloat16(b)) << 16);
}
__device__ __forceinline__ float rbf(float x)
{
    return __bfloat162float(__float2bfloat16(x));
}

// ------------------------ split-bf16 conversion -----------------------------
__global__ __launch_bounds__(256)
void k_cvt_act(const float4* __restrict__ X, uint2* __restrict__ Hh,
               uint2* __restrict__ Hl)
{
    const int i = blockIdx.x * 256 + threadIdx.x;
    float4 x = X[i];
    float hx = rbf(x.x), hy = rbf(x.y), hz = rbf(x.z), hw = rbf(x.w);
    uint2 h; h.x = pack2(hx, hy); h.y = pack2(hz, hw);
    uint2 l; l.x = pack2(x.x - hx, x.y - hy); l.y = pack2(x.z - hz, x.w - hw);
    Hh[i] = h; Hl[i] = l;
}

__global__ void k_cvt_wt(const float* __restrict__ W, __nv_bfloat16* __restrict__ Th,
                         __nv_bfloat16* __restrict__ Tl)
{
    __shared__ float t[32][33];
    const int n0 = blockIdx.x * 32, k0 = blockIdx.y * 32;
    const int tx = threadIdx.x, ty = threadIdx.y;
    #pragma unroll
    for (int j = 0; j < 32; j += 8)
        t[ty + j][tx] = W[(size_t)(k0 + ty + j) * DM + n0 + tx];
    __syncthreads();
    #pragma unroll
    for (int j = 0; j < 32; j += 8) {
        float v = t[tx][ty + j];
        __nv_bfloat16 h = __float2bfloat16(v);
        Th[(size_t)(n0 + ty + j) * DM + k0 + tx] = h;
        Tl[(size_t)(n0 + ty + j) * DM + k0 + tx] =
            __float2bfloat16(v - __bfloat162float(h));
    }
}

__global__ void k_cvt_proj(const float* __restrict__ P)
{
    const int i = blockIdx.x * 256 + threadIdx.x;
    if (i < RR * DH) {
        float v = CNORM * P[i];
        float h = rbf(v);
        g_ph[i] = __float2bfloat16(h);
        g_pl[i] = __float2bfloat16(v - h);
    }
}

// -------------- HMMA GEMM: C[16384,1024] = A @ B^T (+bias) ------------------
#define MCHK  32
#define NCHK  (DM / MCHK)
#define MAT   (128 * 80)
#define STG   (4 * MAT)
#define MM_SMEM (3 * STG)

template <int OUT>
__global__ __launch_bounds__(256)
void k_mm(const __nv_bfloat16* __restrict__ Ah, const __nv_bfloat16* __restrict__ Al,
          const __nv_bfloat16* __restrict__ Bh, const __nv_bfloat16* __restrict__ Bl,
          const float* __restrict__ bias, float* __restrict__ C,
          __nv_bfloat16* __restrict__ Ch, __nv_bfloat16* __restrict__ Cl)
{
    const uint32_t smb = s2u(dynsm);
    const int tid = threadIdx.x, wid = tid >> 5, lane = tid & 31;
    const int bx = blockIdx.x, by = blockIdx.y;
    const int wm = wid & 1, wn = wid >> 1;

    const __nv_bfloat16* gbase[4];
    gbase[0] = Ah + (size_t)(by * 128) * DM;
    gbase[1] = Al + (size_t)(by * 128) * DM;
    gbase[2] = Bh + (size_t)(bx * 128) * DM;
    gbase[3] = Bl + (size_t)(bx * 128) * DM;

    int lmat[8], lrow[8], lq[8];
    #pragma unroll
    for (int t = 0; t < 8; t++) {
        int idx = tid + t * 256;
        lmat[t] = idx >> 9;
        lrow[t] = (idx >> 2) & 127;
        lq[t]   = idx & 3;
    }

    auto issue = [&](int c, int s) {
        const int k0 = c * MCHK;
        #pragma unroll
        for (int t = 0; t < 8; t++) {
            const __nv_bfloat16* gp = gbase[lmat[t]] + (size_t)lrow[t] * DM
                                      + k0 + lq[t] * 8;
            uint32_t sa = smb + s * STG + lmat[t] * MAT + lrow[t] * 80 + lq[t] * 16;
            cp16(sa, gp);
        }
        asm volatile("cp.async.commit_group;");
    };

    issue(0, 0);
    issue(1, 1);
    issue(2, 2);

    const int part = lane >> 3, l8 = lane & 7;
    const int aRow = (part & 1) * 8 + l8, aCol = (part >> 1) * 8;
    const int bRow = (part >> 1) * 8 + l8, bCol = (part & 1) * 8;

    float acc[4][4][4] = {};

    for (int c = 0; c < NCHK; c++) {
        const int s = c % 3;
        asm volatile("cp.async.wait_group 2;");
        __syncthreads();

        const uint32_t sb = smb + s * STG;
        #pragma unroll
        for (int kk = 0; kk < 2; kk++) {
            uint32_t ah[16], al[16], bh[8], bl[8];
            #pragma unroll
            for (int mi = 0; mi < 4; mi++) {
                uint32_t off = (uint32_t)((wm * 64 + mi * 16 + aRow) * 80
                                          + (kk * 16 + aCol) * 2);
                ldm4(&ah[mi * 4], sb + off);
                ldm4(&al[mi * 4], sb + MAT + off);
            }
            #pragma unroll
            for (int f = 0; f < 2; f++) {
                uint32_t off = (uint32_t)((wn * 32 + f * 16 + bRow) * 80
                                          + (kk * 16 + bCol) * 2);
                ldm4(&bh[f * 4], sb + 2 * MAT + off);
                ldm4(&bl[f * 4], sb + 3 * MAT + off);
            }
            #pragma unroll
            for (int mi = 0; mi < 4; mi++)
                #pragma unroll
                for (int ni = 0; ni < 4; ni++) {
                    uint32_t* bph = &bh[(ni >> 1) * 4 + (ni & 1) * 2];
                    uint32_t* bpl = &bl[(ni >> 1) * 4 + (ni & 1) * 2];
                    mma16816(acc[mi][ni], &ah[mi * 4], bph);
                    mma16816(acc[mi][ni], &ah[mi * 4], bpl);
                    mma16816(acc[mi][ni], &al[mi * 4], bph);
                }
        }
        __syncthreads();
        if (c + 3 < NCHK) issue(c + 3, s);
    }

    const int g = lane >> 2, cc = (lane & 3) * 2;
    #pragma unroll
    for (int mi = 0; mi < 4; mi++) {
        const int r0 = by * 128 + wm * 64 + mi * 16 + g;
        #pragma unroll
        for (int ni = 0; ni < 4; ni++) {
            const int col = bx * 128 + wn * 32 + ni * 8 + cc;
            const float b0 = bias[col], b1 = bias[col + 1];
            float v0 = acc[mi][ni][0] + b0, v1 = acc[mi][ni][1] + b1;
            float v2 = acc[mi][ni][2] + b0, v3 = acc[mi][ni][3] + b1;
            if (OUT == 0) {
                *(float2*)(C + (size_t)r0 * DM + col)       = make_float2(v0, v1);
                *(float2*)(C + (size_t)(r0 + 8) * DM + col) = make_float2(v2, v3);
            } else {
                float h0 = rbf(v0), h1 = rbf(v1), h2 = rbf(v2), h3 = rbf(v3);
                *(uint32_t*)(Ch + (size_t)r0 * DM + col)       = pack2(h0, h1);
                *(uint32_t*)(Cl + (size_t)r0 * DM + col)       = pack2(v0 - h0, v1 - h1);
                *(uint32_t*)(Ch + (size_t)(r0 + 8) * DM + col) = pack2(h2, h3);
                *(uint32_t*)(Cl + (size_t)(r0 + 8) * DM + col) = pack2(v2 - h2, v3 - h3);
            }
        }
    }
}

// ----------------- FAVOR+ feature kernel on HMMA ----------------------------
#define F_AH 0
#define F_AL 18432
#define F_BH 36864
#define F_BL 73728
#define F_DG 110592
#define F_K1 111104
#define F_RD 127488
#define FEATM_SMEM 127552

template <bool IS_Q>
__global__ __launch_bounds__(256)
void k_featm(const __nv_bfloat16* __restrict__ Xh, const __nv_bfloat16* __restrict__ Xl,
             __nv_bfloat16* __restrict__ out, const float* __restrict__ k1,
             float* __restrict__ den)
{
    char* smc = (char*)dynsm;
    const uint32_t smb = s2u(smc);
    const int tid = threadIdx.x, w = tid >> 5, lane = tid & 31;
    const int n0 = blockIdx.x * 128;

    {
        const int r = tid >> 1, hf = tid & 1;
        const uint4* sh = (const uint4*)(Xh + (size_t)(n0 + r) * 64 + hf * 32);
        const uint4* sl = (const uint4*)(Xl + (size_t)(n0 + r) * 64 + hf * 32);
        char* dh_ = smc + F_AH + r * 144 + hf * 64;
        char* dl_ = smc + F_AL + r * 144 + hf * 64;
        #pragma unroll
        for (int i = 0; i < 4; i++) {
            *(uint4*)(dh_ + i * 16) = sh[i];
            *(uint4*)(dl_ + i * 16) = sl[i];
        }
    }
    {
        const uint4* sh = (const uint4*)(g_ph + tid * 64);
        const uint4* sl = (const uint4*)(g_pl + tid * 64);
        char* dh_ = smc + F_BH + tid * 144;
        char* dl_ = smc + F_BL + tid * 144;
        #pragma unroll
        for (int i = 0; i < 8; i++) {
            *(uint4*)(dh_ + i * 16) = sh[i];
            *(uint4*)(dl_ + i * 16) = sl[i];
        }
    }
    if (IS_Q) {
        const int b = n0 >> 16;
        const float4* src = (const float4*)(k1 + b * 4096);
        float4* dst = (float4*)(smc + F_K1);
        #pragma unroll
        for (int j = 0; j < 4; j++)
            dst[tid * 4 + j] = src[tid * 4 + j];
    }
    __syncthreads();

    if (tid < 128) {
        const __nv_bfloat162* ph = (const __nv_bfloat162*)(smc + F_AH + tid * 144);
        const __nv_bfloat162* pl = (const __nv_bfloat162*)(smc + F_AL + tid * 144);
        float ss = 0.f;
        #pragma unroll
        for (int i = 0; i < 32; i++) {
            float2 h = __bfloat1622float2(ph[i]);
            float2 l = __bfloat1622float2(pl[i]);
            float x0 = h.x + l.x, x1 = h.y + l.y;
            ss = fmaf(x0, x0, ss);
            ss = fmaf(x1, x1, ss);
        }
        ((float*)(smc + F_DG))[tid] = 0.0625f * ss;
    }
    __syncthreads();

    const int part = lane >> 3, l8 = lane & 7;
    const int aRow = (part & 1) * 8 + l8, aCol = (part >> 1) * 8;
    const int bRow = (part >> 1) * 8 + l8, bCol = (part & 1) * 8;

    float acc[32][4];
    #pragma unroll
    for (int i = 0; i < 32; i++)
        #pragma unroll
        for (int j = 0; j < 4; j++) acc[i][j] = 0.f;

    #pragma unroll
    for (int ks = 0; ks < 4; ks++) {
        uint32_t ah[4], al[4];
        const uint32_t aoff = (uint32_t)((16 * w + aRow) * 144 + (ks * 16 + aCol) * 2);
        ldm4(ah, smb + F_AH + aoff);
        ldm4(al, smb + F_AL + aoff);
        #pragma unroll
        for (int p = 0; p < 16; p++) {
            uint32_t bh[4], bl[4];
            const uint32_t boff = (uint32_t)((p * 16 + bRow) * 144 + (ks * 16 + bCol) * 2);
            ldm4(bh, smb + F_BH + boff);
            ldm4(bl, smb + F_BL + boff);
            mma16816(acc[2 * p],     ah, &bh[0]);
            mma16816(acc[2 * p],     ah, &bl[0]);
            mma16816(acc[2 * p],     al, &bh[0]);
            mma16816(acc[2 * p + 1], ah, &bh[2]);
            mma16816(acc[2 * p + 1], ah, &bl[2]);
            mma16816(acc[2 * p + 1], al, &bh[2]);
        }
    }

    const int g = lane >> 2, cc = (lane & 3) * 2;
    const int lr0 = 16 * w + g;
    const float d0 = ((float*)(smc + F_DG))[lr0];
    const float d1 = ((float*)(smc + F_DG))[lr0 + 8];

    if (IS_Q) {
        float m0 = -3.0e38f, m1 = -3.0e38f;
        #pragma unroll
        for (int nf = 0; nf < 32; nf++) {
            m0 = fmaxf(m0, fmaxf(acc[nf][0], acc[nf][1]));
            m1 = fmaxf(m1, fmaxf(acc[nf][2], acc[nf][3]));
        }
        m0 = fmaxf(m0, __shfl_xor_sync(0xffffffffu, m0, 1));
        m0 = fmaxf(m0, __shfl_xor_sync(0xffffffffu, m0, 2));
        m1 = fmaxf(m1, __shfl_xor_sync(0xffffffffu, m1, 1));
        m1 = fmaxf(m1, __shfl_xor_sync(0xffffffffu, m1, 2));
        const float s0 = d0 + m0, s1 = d1 + m1;
        const int h0 = lr0 & 15, h1 = (lr0 + 8) & 15;
        const float* k1s = (const float*)(smc + F_K1);
        float dp0 = 0.f, dp1 = 0.f;
        #pragma unroll
        for (int nf = 0; nf < 32; nf++) {
            const int col = nf * 8 + cc;
            float v0 = rbf(RATIO * (fexp(acc[nf][0] - s0) + 1e-4f));
            float v1 = rbf(RATIO * (fexp(acc[nf][1] - s0) + 1e-4f));
            float v2 = rbf(RATIO * (fexp(acc[nf][2] - s1) + 1e-4f));
            float v3 = rbf(RATIO * (fexp(acc[nf][3] - s1) + 1e-4f));
            *(uint32_t*)(out + (size_t)(n0 + lr0) * 256 + col)     = pack2(v0, v1);
            *(uint32_t*)(out + (size_t)(n0 + lr0 + 8) * 256 + col) = pack2(v2, v3);
            dp0 = fmaf(v0, k1s[h0 * 256 + col], dp0);
            dp0 = fmaf(v1, k1s[h0 * 256 + col + 1], dp0);
            dp1 = fmaf(v2, k1s[h1 * 256 + col], dp1);
            dp1 = fmaf(v3, k1s[h1 * 256 + col + 1], dp1);
        }
        dp0 += __shfl_xor_sync(0xffffffffu, dp0, 1);
        dp0 += __shfl_xor_sync(0xffffffffu, dp0, 2);
        dp1 += __shfl_xor_sync(0xffffffffu, dp1, 1);
        dp1 += __shfl_xor_sync(0xffffffffu, dp1, 2);
        if ((lane & 3) == 0) {
            den[n0 + lr0]     = dp0;
            den[n0 + lr0 + 8] = dp1;
        }
    } else {
        float wmax = -3.0e38f;
        #pragma unroll
        for (int nf = 0; nf < 32; nf++) {
            const int col = nf * 8 + cc;
            wmax = fmaxf(wmax, fmaxf(fmaxf(acc[nf][0], acc[nf][1]),
                                     fmaxf(acc[nf][2], acc[nf][3])));
            float v0 = fexp(acc[nf][0] - d0);
            float v1 = fexp(acc[nf][1] - d0);
            float v2 = fexp(acc[nf][2] - d1);
            float v3 = fexp(acc[nf][3] - d1);
            *(uint32_t*)(out + (size_t)(n0 + lr0) * 256 + col)     = pack2(v0, v1);
            *(uint32_t*)(out + (size_t)(n0 + lr0 + 8) * 256 + col) = pack2(v2, v3);
        }
        #pragma unroll
        for (int o = 16; o > 0; o >>= 1)
            wmax = fmaxf(wmax, __shfl_xor_sync(0xffffffffu, wmax, o));
        float* red = (float*)(smc + F_RD);
        if (lane == 0) red[w] = wmax;
        __syncthreads();
        if (tid == 0) {
            float m = red[0];
            #pragma unroll
            for (int i = 1; i < 8; i++) m = fmaxf(m, red[i]);
            atomicMaxF(&g_kmax, m);
        }
    }
}

// ---- kv partials on HMMA: C[256 r][64 v] = u^T @ (vh+vl) per (bh, chunk) ---
// u: [s][r] in gmem; v split-bf16 [s][v]. Both operands via ldmatrix.trans.
#define KVU_STR 528
#define KVV_STR 144
#define KVU_STG (16*KVU_STR)       // 8448
#define KVV_STG (16*KVV_STR)       // 2304
#define KV_VH0  (3*KVU_STG)        // 25344
#define KV_VL0  (KV_VH0 + 3*KVV_STG)
#define KV_SMEM (KV_VL0 + 3*KVV_STG)   // 39168

__global__ __launch_bounds__(256)
void k_kv()
{
    char* smc = (char*)dynsm;
    const uint32_t smb = s2u(smc);
    const int bh = blockIdx.x, c = blockIdx.y;
    const int b = bh >> 4, h = bh & 15;
    const int tid = threadIdx.x, w = tid >> 5, lane = tid & 31;
    const int sbase = b * S_ + c * SCH;

    // loader coords
    const int urow0 = tid >> 5,       ucol0 = tid & 31;
    const int urow1 = urow0 + 8;      // (tid+256)>>5
    const int half = tid >> 7, rem = tid & 127;
    const int vrow = rem >> 3, vq = rem & 7;
    const __nv_bfloat16* usrc0 = g_u + ((size_t)(sbase + urow0) * H_ + h) * RR + ucol0 * 8;
    const __nv_bfloat16* usrc1 = g_u + ((size_t)(sbase + urow1) * H_ + h) * RR + ucol0 * 8;
    const __nv_bfloat16* vsrc = (half ? g_vl : g_vh)
                                + (size_t)(sbase + vrow) * DM + h * DH + vq * 8;
    const uint32_t ud0 = smb + urow0 * KVU_STR + ucol0 * 16;
    const uint32_t ud1 = smb + urow1 * KVU_STR + ucol0 * 16;
    const uint32_t vd  = smb + (half ? KV_VL0 : KV_VH0) + vrow * KVV_STR + vq * 16;

    auto issue = [&](int i) {
        const int stg = i % 3;
        const size_t ua = (size_t)i * 16 * (H_ * RR);
        const size_t va = (size_t)i * 16 * DM;
        cp16(ud0 + stg * KVU_STG, usrc0 + ua);
        cp16(ud1 + stg * KVU_STG, usrc1 + ua);
        cp16(vd  + stg * KVV_STG, vsrc + va);
        asm volatile("cp.async.commit_group;");
    };
    issue(0); issue(1); issue(2);

    const int part = lane >> 3, l8 = lane & 7;
    const int a_srow = (part >> 1) * 8 + l8, a_rcol = (part & 1) * 8;
    const int b_srow = (part & 1) * 8 + l8, b_vcol = (part >> 1) * 8;

    float acc[2][8][4];
    #pragma unroll
    for (int i = 0; i < 2; i++)
        #pragma unroll
        for (int j = 0; j < 8; j++)
            #pragma unroll
            for (int k = 0; k < 4; k++) acc[i][j][k] = 0.f;
    float u1 = 0.f, v1 = 0.f;

    for (int i = 0; i < 32; i++) {
        asm volatile("cp.async.wait_group 2;");
        __syncthreads();
        const int stg = i % 3;
        const uint32_t ub  = smb + stg * KVU_STG;
        const uint32_t vhb = smb + KV_VH0 + stg * KVV_STG;
        const uint32_t vlb = smb + KV_VL0 + stg * KVV_STG;

        uint32_t af[2][4], bhf[4][4], blf[4][4];
        #pragma unroll
        for (int mi = 0; mi < 2; mi++)
            ldm4t(af[mi], ub + a_srow * KVU_STR + (w * 32 + mi * 16 + a_rcol) * 2);
        #pragma unroll
        for (int nb = 0; nb < 4; nb++) {
            const uint32_t off = b_srow * KVV_STR + (nb * 16 + b_vcol) * 2;
            ldm4t(bhf[nb], vhb + off);
            ldm4t(blf[nb], vlb + off);
        }
        #pragma unroll
        for (int mi = 0; mi < 2; mi++)
            #pragma unroll
            for (int ni = 0; ni < 8; ni++) {
                mma16816(acc[mi][ni], af[mi], &bhf[ni >> 1][(ni & 1) * 2]);
                mma16816(acc[mi][ni], af[mi], &blf[ni >> 1][(ni & 1) * 2]);
            }
        // column sums from smem
        const char* uu = smc + stg * KVU_STG;
        #pragma unroll
        for (int s = 0; s < 16; s++)
            u1 += __bfloat162float(*(const __nv_bfloat16*)(uu + s * KVU_STR + tid * 2));
        if (tid < 64) {
            const char* vh_ = smc + KV_VH0 + stg * KVV_STG;
            const char* vl_ = smc + KV_VL0 + stg * KVV_STG;
            #pragma unroll
            for (int s = 0; s < 16; s++)
                v1 += __bfloat162float(*(const __nv_bfloat16*)(vh_ + s * KVV_STR + tid * 2))
                    + __bfloat162float(*(const __nv_bfloat16*)(vl_ + s * KVV_STR + tid * 2));
        }
        __syncthreads();
        if (i + 3 < 32) issue(i + 3);
    }

    const int g = lane >> 2, cc = (lane & 3) * 2;
    const int pb = c * BH + bh;
    float* kp = g_kvp + (size_t)pb * (RR * DH);
    #pragma unroll
    for (int mi = 0; mi < 2; mi++) {
        const int r0 = w * 32 + mi * 16 + g;
        #pragma unroll
        for (int ni = 0; ni < 8; ni++) {
            const int col = ni * 8 + cc;
            *(float2*)(kp + r0 * DH + col)       = make_float2(acc[mi][ni][0], acc[mi][ni][1]);
            *(float2*)(kp + (r0 + 8) * DH + col) = make_float2(acc[mi][ni][2], acc[mi][ni][3]);
        }
    }
    g_u1p[pb * RR + tid] = u1;
    if (tid < 64) g_v1p[pb * DH + tid] = v1;
}

__global__ void k_red()
{
    const int bh = blockIdx.x, t = threadIdx.x;
    const float a = RATIO * fexp(-g_kmax);
    float s = 0.f;
    #pragma unroll
    for (int c = 0; c < SPLIT; c++) s += g_u1p[(c * BH + bh) * RR + t];
    g_k1[bh * RR + t] = a * s + RATIO * 1e-4f * (float)S_;
    if (t < DH) {
        float vs = 0.f;
        #pragma unroll
        for (int c = 0; c < SPLIT; c++) vs += g_v1p[(c * BH + bh) * DH + t];
        g_v1[bh * DH + t] = vs;
    }
}

// kv final: reduce partials, fold a + eps*v1, emit TRANSPOSED split-bf16 [v][r]
__global__ void k_kvred()
{
    const int bh = blockIdx.x, r = blockIdx.y, v = threadIdx.x;
    const float a = RATIO * fexp(-g_kmax);
    float s = 0.f;
    #pragma unroll
    for (int c = 0; c < SPLIT; c++)
        s += g_kvp[((size_t)(c * BH + bh) * RR + r) * DH + v];
    const float val = a * s + RATIO * 1e-4f * g_v1[bh * DH + v];
    const float hv = rbf(val);
    g_kvfh[(size_t)bh * (DH * RR) + v * RR + r] = __float2bfloat16(hv);
    g_kvfl[(size_t)bh * (DH * RR) + v * RR + r] = __float2bfloat16(val - hv);
}

// ---- attention out on HMMA: qhat[128,256] @ kvfT[256,64], /den, bf16 hi/lo --
#define AT_A  0
#define AT_BH (128 * 528)                  // 67584
#define AT_BL (AT_BH + 64 * 528)           // 101376
#define AT_SMEM (AT_BL + 64 * 528)         // 135168

__global__ __launch_bounds__(256)
void k_att()
{
    char* smc = (char*)dynsm;
    const uint32_t smb = s2u(smc);
    const int bh = blockIdx.x, sc = blockIdx.y;
    const int b = bh >> 4, h = bh & 15;
    const int tid = threadIdx.x, w = tid >> 5, lane = tid & 31;

    // load A: qhat rows sc*128..+128, 512B each
    #pragma unroll
    for (int t = 0; t < 16; t++) {
        const int idx = tid + t * 256;
        const int row = idx >> 5, col = idx & 31;
        cp16(smb + AT_A + row * 528 + col * 16,
             g_qhat + ((size_t)(b * S_ + sc * 128 + row) * H_ + h) * RR + col * 8);
    }
    // load B: kvfT hi/lo, 64 rows x 512B each
    #pragma unroll
    for (int t = 0; t < 16; t++) {
        const int idx = tid + t * 256;
        const int hf = idx >> 11, rem = idx & 2047;
        const int row = rem >> 5, col = rem & 31;
        cp16(smb + (hf ? AT_BL : AT_BH) + row * 528 + col * 16,
             (hf ? g_kvfl : g_kvfh) + (size_t)bh * (DH * RR) + row * RR + col * 8);
    }
    asm volatile("cp.async.commit_group;");
    asm volatile("cp.async.wait_group 0;");
    __syncthreads();

    const int part = lane >> 3, l8 = lane & 7;
    const int aRow = (part & 1) * 8 + l8, aCol = (part >> 1) * 8;
    const int bRow = (part >> 1) * 8 + l8, bCol = (part & 1) * 8;

    float acc[8][4];
    #pragma unroll
    for (int i = 0; i < 8; i++)
        #pragma unroll
        for (int j = 0; j < 4; j++) acc[i][j] = 0.f;

    #pragma unroll
    for (int kk = 0; kk < 16; kk++) {
        uint32_t af[4];
        ldm4(af, smb + AT_A + (w * 16 + aRow) * 528 + (kk * 16 + aCol) * 2);
        uint32_t bhf[4][4], blf[4][4];
        #pragma unroll
        for (int nb = 0; nb < 4; nb++) {
            const uint32_t off = (nb * 16 + bRow) * 528 + (kk * 16 + bCol) * 2;
            ldm4(bhf[nb], smb + AT_BH + off);
            ldm4(blf[nb], smb + AT_BL + off);
        }
        #pragma unroll
        for (int ni = 0; ni < 8; ni++) {
            mma16816(acc[ni], af, &bhf[ni >> 1][(ni & 1) * 2]);
            mma16816(acc[ni], af, &blf[ni >> 1][(ni & 1) * 2]);
        }
    }

    const int g = lane >> 2, cc = (lane & 3) * 2;
    #pragma unroll
    for (int hf = 0; hf < 2; hf++) {
        const int s = sc * 128 + w * 16 + g + hf * 8;
        const int n = (b * S_ + s) * H_ + h;
        const float inv = 1.0f / g_den[n];
        const size_t ob = (size_t)(b * S_ + s) * DM + h * DH;
        #pragma unroll
        for (int ni = 0; ni < 8; ni++) {
            const int col = ni * 8 + cc;
            const float v0 = acc[ni][hf * 2] * inv;
            const float v1 = acc[ni][hf * 2 + 1] * inv;
            const float h0 = rbf(v0), h1 = rbf(v1);
            *(uint32_t*)(g_ah + ob + col) = pack2(h0, h1);
            *(uint32_t*)(g_al + ob + col) = pack2(v0 - h0, v1 - h1);
        }
    }
}

// ---------------------------------------------------------------------------
extern "C" void kernel_launch(void* const* d_in, const int* in_sizes, int n_in,
                              void* d_out, int out_size)
{
    const float* query = (const float*)d_in[0];
    const float* key   = (const float*)d_in[1];
    const float* value = (const float*)d_in[2];
    const float* Wq    = (const float*)d_in[3];
    const float* bq    = (const float*)d_in[4];
    const float* Wk    = (const float*)d_in[5];
    const float* bk    = (const float*)d_in[6];
    const float* Wv    = (const float*)d_in[7];
    const float* bv    = (const float*)d_in[8];
    const float* Wo    = (const float*)d_in[9];
    const float* bo    = (const float*)d_in[10];
    const float* proj  = (const float*)d_in[11];
    float* out = (float*)d_out;

    void *pvh, *pvl, *pqh, *pql, *pkh, *pkl, *pqf, *pu, *pk1, *pden,
         *pah, *pal, *pwh, *pwl;
    cudaGetSymbolAddress(&pvh, g_vh);
    cudaGetSymbolAddress(&pvl, g_vl);
    cudaGetSymbolAddress(&pqh, g_qh);
    cudaGetSymbolAddress(&pql, g_ql);
    cudaGetSymbolAddress(&pkh, g_kh);
    cudaGetSymbolAddress(&pkl, g_kl);
    cudaGetSymbolAddress(&pqf, g_qhat);
    cudaGetSymbolAddress(&pu,  g_u);
    cudaGetSymbolAddress(&pk1, g_k1);
    cudaGetSymbolAddress(&pden, g_den);
    cudaGetSymbolAddress(&pah, g_ah);
    cudaGetSymbolAddress(&pal, g_al);
    cudaGetSymbolAddress(&pwh, g_wh);
    cudaGetSymbolAddress(&pwl, g_wl);

    cudaFuncSetAttribute(k_mm<0>, cudaFuncAttributeMaxDynamicSharedMemorySize, MM_SMEM);
    cudaFuncSetAttribute(k_mm<1>, cudaFuncAttributeMaxDynamicSharedMemorySize, MM_SMEM);
    cudaFuncSetAttribute(k_featm<true>,  cudaFuncAttributeMaxDynamicSharedMemorySize, FEATM_SMEM);
    cudaFuncSetAttribute(k_featm<false>, cudaFuncAttributeMaxDynamicSharedMemorySize, FEATM_SMEM);
    cudaFuncSetAttribute(k_kv, cudaFuncAttributeMaxDynamicSharedMemorySize, KV_SMEM);
    cudaFuncSetAttribute(k_att, cudaFuncAttributeMaxDynamicSharedMemorySize, AT_SMEM);

    __nv_bfloat16* ah = (__nv_bfloat16*)pah;
    __nv_bfloat16* al = (__nv_bfloat16*)pal;
    __nv_bfloat16* wh = (__nv_bfloat16*)pwh;
    __nv_bfloat16* wl = (__nv_bfloat16*)pwl;

    const int CVT_G = MROWS * DM / 4 / 256;
    const dim3 WT_G(DM / 32, DM / 32);
    const dim3 WT_B(32, 8);
    const dim3 MM_G(DM / 128, MROWS / 128);

    k_init<<<1, 1>>>();
    k_cvt_proj<<<64, 256>>>(proj);

    // Q = query @ Wq + bq  -> split bf16
    k_cvt_act<<<CVT_G, 256>>>((const float4*)query, (uint2*)ah, (uint2*)al);
    k_cvt_wt<<<WT_G, WT_B>>>(Wq, wh, wl);
    k_mm<1><<<MM_G, 256, MM_SMEM>>>(ah, al, wh, wl, bq, nullptr,
                                    (__nv_bfloat16*)pqh, (__nv_bfloat16*)pql);
    // K = key @ Wk + bk  -> split bf16
    k_cvt_act<<<CVT_G, 256>>>((const float4*)key, (uint2*)ah, (uint2*)al);
    k_cvt_wt<<<WT_G, WT_B>>>(Wk, wh, wl);
    k_mm<1><<<MM_G, 256, MM_SMEM>>>(ah, al, wh, wl, bk, nullptr,
                                    (__nv_bfloat16*)pkh, (__nv_bfloat16*)pkl);
    // V = value @ Wv + bv -> split bf16
    k_cvt_act<<<CVT_G, 256>>>((const float4*)value, (uint2*)ah, (uint2*)al);
    k_cvt_wt<<<WT_G, WT_B>>>(Wv, wh, wl);
    k_mm<1><<<MM_G, 256, MM_SMEM>>>(ah, al, wh, wl, bv, nullptr,
                                    (__nv_bfloat16*)pvh, (__nv_bfloat16*)pvl);

    // key feature path first
    k_featm<false><<<NROWS / 128, 256, FEATM_SMEM>>>(
        (const __nv_bfloat16*)pkh, (const __nv_bfloat16*)pkl,
        (__nv_bfloat16*)pu, nullptr, nullptr);
    k_kv<<<dim3(BH, SPLIT), 256, KV_SMEM>>>();
    k_red<<<BH, 256>>>();
    k_kvred<<<dim3(BH, RR), DH>>>();

    k_featm<true><<<NROWS / 128, 256, FEATM_SMEM>>>(
        (const __nv_bfloat16*)pqh, (const __nv_bfloat16*)pql,
        (__nv_bfloat16*)pqf, (const float*)pk1, (float*)pden);
    k_att<<<dim3(BH, S_ / 128), 256, AT_SMEM>>>();

    // out = att @ Wo + bo
    k_cvt_wt<<<WT_G, WT_B>>>(Wo, wh, wl);
    k_mm<0><<<MM_G, 256, MM_SMEM>>>(ah, al, wh, wl, bo, out, nullptr, nullptr);
}

// round 16
// speedup vs baseline: 1.4401x; 1.0309x over previous
#include <cuda_runtime.h>
#include <cuda_bf16.h>
#include <cstdint>

// ---------------------------------------------------------------------------
// Performer attention. B=4, S=4096, Dm=1024, H=16, Dh=64, R=256
// All GEMM work (projections, features, kv, attention) on mma.sync HMMA.
// k_mm: 4-stage cp.async pipeline, ONE sync per K-chunk.
// ---------------------------------------------------------------------------

#define B_    4
#define S_    4096
#define DM    1024
#define H_    16
#define DH    64
#define RR    256
#define MROWS (B_*S_)        // 16384
#define NROWS (B_*S_*H_)     // 262144
#define BH    (B_*H_)        // 64
#define SPLIT 8
#define SCH   (S_/SPLIT)     // 512

#define RATIO 0.0625f
#define CNORM 0.35355339059327373f

// ------------------------------ scratch ------------------------------------
__device__ __nv_bfloat16 g_vh[MROWS*DM];
__device__ __nv_bfloat16 g_vl[MROWS*DM];
__device__ __nv_bfloat16 g_qh[MROWS*DM];
__device__ __nv_bfloat16 g_ql[MROWS*DM];
__device__ __nv_bfloat16 g_kh[MROWS*DM];
__device__ __nv_bfloat16 g_kl[MROWS*DM];
__device__ __nv_bfloat16 g_qhat[NROWS*RR];
__device__ __nv_bfloat16 g_u[NROWS*RR];
__device__ __nv_bfloat16 g_ph[RR*DH];
__device__ __nv_bfloat16 g_pl[RR*DH];
__device__ __nv_bfloat16 g_kvfh[BH*DH*RR];   // kv final, TRANSPOSED [bh][v][r]
__device__ __nv_bfloat16 g_kvfl[BH*DH*RR];
__device__ float g_den[NROWS];
__device__ float g_kvp[SPLIT*BH*RR*DH];
__device__ float g_u1p[SPLIT*BH*RR];
__device__ float g_v1p[SPLIT*BH*DH];
__device__ float g_k1[BH*RR];
__device__ float g_v1[BH*DH];
__device__ float g_kmax;
__device__ __nv_bfloat16 g_ah[MROWS*DM];
__device__ __nv_bfloat16 g_al[MROWS*DM];
__device__ __nv_bfloat16 g_wh[DM*DM];
__device__ __nv_bfloat16 g_wl[DM*DM];

extern __shared__ float dynsm[];

// ------------------------- FMA-pipe exp (no MUFU) --------------------------
__device__ __forceinline__ float fexp(float x)
{
    x = fminf(fmaxf(x, -87.0f), 87.0f);
    float z = x * 1.4426950408889634f;
    float t = z + 12582912.0f;
    int   n = __float_as_int(t) - 0x4B400000;
    float f = z - (t - 12582912.0f);
    float p = 1.3333558e-3f;
    p = fmaf(p, f, 9.6181291e-3f);
    p = fmaf(p, f, 5.5504109e-2f);
    p = fmaf(p, f, 2.4022651e-1f);
    p = fmaf(p, f, 6.9314718e-1f);
    p = fmaf(p, f, 1.0f);
    return p * __int_as_float((n + 127) << 23);
}

__device__ __forceinline__ void atomicMaxF(float* addr, float v)
{
    int* ia = (int*)addr;
    int old = *ia;
    while (__int_as_float(old) < v) {
        int assumed = old;
        old = atomicCAS(ia, assumed, __float_as_int(v));
        if (old == assumed) break;
    }
}

__global__ void k_init() { g_kmax = -3.0e38f; }

// ----------------------- PTX helpers ---------------------------------------
__device__ __forceinline__ uint32_t s2u(const void* p)
{
    uint32_t a;
    asm("{ .reg .u64 t; cvta.to.shared.u64 t, %1; cvt.u32.u64 %0, t; }"
        : "=r"(a) : "l"(p));
    return a;
}
__device__ __forceinline__ void cp16(uint32_t s, const void* g)
{
    asm volatile("cp.async.cg.shared.global [%0], [%1], 16;"
                 :: "r"(s), "l"(g));
}
__device__ __forceinline__ void ldm4(uint32_t* r, uint32_t addr)
{
    asm volatile("ldmatrix.sync.aligned.m8n8.x4.shared.b16 {%0,%1,%2,%3}, [%4];"
                 : "=r"(r[0]), "=r"(r[1]), "=r"(r[2]), "=r"(r[3]) : "r"(addr));
}
__device__ __forceinline__ void ldm4t(uint32_t* r, uint32_t addr)
{
    asm volatile("ldmatrix.sync.aligned.m8n8.x4.trans.shared.b16 {%0,%1,%2,%3}, [%4];"
                 : "=r"(r[0]), "=r"(r[1]), "=r"(r[2]), "=r"(r[3]) : "r"(addr));
}
__device__ __forceinline__ void mma16816(float* c, const uint32_t* a,
                                         const uint32_t* b)
{
    asm volatile("mma.sync.aligned.m16n8k16.row.col.f32.bf16.bf16.f32 "
                 "{%0,%1,%2,%3}, {%4,%5,%6,%7}, {%8,%9}, {%0,%1,%2,%3};"
                 : "+f"(c[0]), "+f"(c[1]), "+f"(c[2]), "+f"(c[3])
                 : "r"(a[0]), "r"(a[1]), "r"(a[2]), "r"(a[3]),
                   "r"(b[0]), "r"(b[1]));
}
__device__ __forceinline__ uint32_t pack2(float a, float b)
{
    return (uint32_t)__bfloat16_as_ushort(__float2bfloat16(a))
         | ((uint32_t)__bfloat16_as_ushort(__float2bfloat16(b)) << 16);
}
__device__ __forceinline__ float rbf(float x)
{
    return __bfloat162float(__float2bfloat16(x));
}

// ------------------------ split-bf16 conversion -----------------------------
__global__ __launch_bounds__(256)
void k_cvt_act(const float4* __restrict__ X, uint2* __restrict__ Hh,
               uint2* __restrict__ Hl)
{
    const int i = blockIdx.x * 256 + threadIdx.x;
    float4 x = X[i];
    float hx = rbf(x.x), hy = rbf(x.y), hz = rbf(x.z), hw = rbf(x.w);
    uint2 h; h.x = pack2(hx, hy); h.y = pack2(hz, hw);
    uint2 l; l.x = pack2(x.x - hx, x.y - hy); l.y = pack2(x.z - hz, x.w - hw);
    Hh[i] = h; Hl[i] = l;
}

__global__ void k_cvt_wt(const float* __restrict__ W, __nv_bfloat16* __restrict__ Th,
                         __nv_bfloat16* __restrict__ Tl)
{
    __shared__ float t[32][33];
    const int n0 = blockIdx.x * 32, k0 = blockIdx.y * 32;
    const int tx = threadIdx.x, ty = threadIdx.y;
    #pragma unroll
    for (int j = 0; j < 32; j += 8)
        t[ty + j][tx] = W[(size_t)(k0 + ty + j) * DM + n0 + tx];
    __syncthreads();
    #pragma unroll
    for (int j = 0; j < 32; j += 8) {
        float v = t[tx][ty + j];
        __nv_bfloat16 h = __float2bfloat16(v);
        Th[(size_t)(n0 + ty + j) * DM + k0 + tx] = h;
        Tl[(size_t)(n0 + ty + j) * DM + k0 + tx] =
            __float2bfloat16(v - __bfloat162float(h));
    }
}

__global__ void k_cvt_proj(const float* __restrict__ P)
{
    const int i = blockIdx.x * 256 + threadIdx.x;
    if (i < RR * DH) {
        float v = CNORM * P[i];
        float h = rbf(v);
        g_ph[i] = __float2bfloat16(h);
        g_pl[i] = __float2bfloat16(v - h);
    }
}

// -------------- HMMA GEMM: C[16384,1024] = A @ B^T (+bias) ------------------
// 128x128 tile, 256 thr, K-chunk 32, 4-stage cp.async, ONE sync per chunk.
#define MCHK  32
#define NCHK  (DM / MCHK)
#define MAT   (128 * 80)
#define STG   (4 * MAT)            // 40960
#define MM_SMEM (4 * STG)          // 163840

template <int OUT>
__global__ __launch_bounds__(256)
void k_mm(const __nv_bfloat16* __restrict__ Ah, const __nv_bfloat16* __restrict__ Al,
          const __nv_bfloat16* __restrict__ Bh, const __nv_bfloat16* __restrict__ Bl,
          const float* __restrict__ bias, float* __restrict__ C,
          __nv_bfloat16* __restrict__ Ch, __nv_bfloat16* __restrict__ Cl)
{
    const uint32_t smb = s2u(dynsm);
    const int tid = threadIdx.x, wid = tid >> 5, lane = tid & 31;
    const int bx = blockIdx.x, by = blockIdx.y;
    const int wm = wid & 1, wn = wid >> 1;

    const __nv_bfloat16* gbase[4];
    gbase[0] = Ah + (size_t)(by * 128) * DM;
    gbase[1] = Al + (size_t)(by * 128) * DM;
    gbase[2] = Bh + (size_t)(bx * 128) * DM;
    gbase[3] = Bl + (size_t)(bx * 128) * DM;

    int lmat[8], lrow[8], lq[8];
    #pragma unroll
    for (int t = 0; t < 8; t++) {
        int idx = tid + t * 256;
        lmat[t] = idx >> 9;
        lrow[t] = (idx >> 2) & 127;
        lq[t]   = idx & 3;
    }

    auto issue = [&](int c) {
        const int k0 = c * MCHK;
        const uint32_t sb = smb + (uint32_t)(c & 3) * STG;
        #pragma unroll
        for (int t = 0; t < 8; t++) {
            const __nv_bfloat16* gp = gbase[lmat[t]] + (size_t)lrow[t] * DM
                                      + k0 + lq[t] * 8;
            cp16(sb + lmat[t] * MAT + lrow[t] * 80 + lq[t] * 16, gp);
        }
        asm volatile("cp.async.commit_group;");
    };

    issue(0); issue(1); issue(2);

    const int part = lane >> 3, l8 = lane & 7;
    const int aRow = (part & 1) * 8 + l8, aCol = (part >> 1) * 8;
    const int bRow = (part >> 1) * 8 + l8, bCol = (part & 1) * 8;

    float acc[4][4][4] = {};

    for (int c = 0; c < NCHK; c++) {
        asm volatile("cp.async.wait_group 2;");
        __syncthreads();
        if (c + 3 < NCHK) issue(c + 3);   // writes stage (c+3)&3 != c&3

        const uint32_t sb = smb + (uint32_t)(c & 3) * STG;
        #pragma unroll
        for (int kk = 0; kk < 2; kk++) {
            uint32_t ah[16], al[16], bh[8], bl[8];
            #pragma unroll
            for (int mi = 0; mi < 4; mi++) {
                uint32_t off = (uint32_t)((wm * 64 + mi * 16 + aRow) * 80
                                          + (kk * 16 + aCol) * 2);
                ldm4(&ah[mi * 4], sb + off);
                ldm4(&al[mi * 4], sb + MAT + off);
            }
            #pragma unroll
            for (int f = 0; f < 2; f++) {
                uint32_t off = (uint32_t)((wn * 32 + f * 16 + bRow) * 80
                                          + (kk * 16 + bCol) * 2);
                ldm4(&bh[f * 4], sb + 2 * MAT + off);
                ldm4(&bl[f * 4], sb + 3 * MAT + off);
            }
            #pragma unroll
            for (int mi = 0; mi < 4; mi++)
                #pragma unroll
                for (int ni = 0; ni < 4; ni++) {
                    uint32_t* bph = &bh[(ni >> 1) * 4 + (ni & 1) * 2];
                    uint32_t* bpl = &bl[(ni >> 1) * 4 + (ni & 1) * 2];
                    mma16816(acc[mi][ni], &ah[mi * 4], bph);
                    mma16816(acc[mi][ni], &ah[mi * 4], bpl);
                    mma16816(acc[mi][ni], &al[mi * 4], bph);
                }
        }
    }

    const int g = lane >> 2, cc = (lane & 3) * 2;
    #pragma unroll
    for (int mi = 0; mi < 4; mi++) {
        const int r0 = by * 128 + wm * 64 + mi * 16 + g;
        #pragma unroll
        for (int ni = 0; ni < 4; ni++) {
            const int col = bx * 128 + wn * 32 + ni * 8 + cc;
            const float b0 = bias[col], b1 = bias[col + 1];
            float v0 = acc[mi][ni][0] + b0, v1 = acc[mi][ni][1] + b1;
            float v2 = acc[mi][ni][2] + b0, v3 = acc[mi][ni][3] + b1;
            if (OUT == 0) {
                *(float2*)(C + (size_t)r0 * DM + col)       = make_float2(v0, v1);
                *(float2*)(C + (size_t)(r0 + 8) * DM + col) = make_float2(v2, v3);
            } else {
                float h0 = rbf(v0), h1 = rbf(v1), h2 = rbf(v2), h3 = rbf(v3);
                *(uint32_t*)(Ch + (size_t)r0 * DM + col)       = pack2(h0, h1);
                *(uint32_t*)(Cl + (size_t)r0 * DM + col)       = pack2(v0 - h0, v1 - h1);
                *(uint32_t*)(Ch + (size_t)(r0 + 8) * DM + col) = pack2(h2, h3);
                *(uint32_t*)(Cl + (size_t)(r0 + 8) * DM + col) = pack2(v2 - h2, v3 - h3);
            }
        }
    }
}

// ----------------- FAVOR+ feature kernel on HMMA ----------------------------
#define F_AH 0
#define F_AL 18432
#define F_BH 36864
#define F_BL 73728
#define F_DG 110592
#define F_K1 111104
#define F_RD 127488
#define FEATM_SMEM 127552

template <bool IS_Q>
__global__ __launch_bounds__(256)
void k_featm(const __nv_bfloat16* __restrict__ Xh, const __nv_bfloat16* __restrict__ Xl,
             __nv_bfloat16* __restrict__ out, const float* __restrict__ k1,
             float* __restrict__ den)
{
    char* smc = (char*)dynsm;
    const uint32_t smb = s2u(smc);
    const int tid = threadIdx.x, w = tid >> 5, lane = tid & 31;
    const int n0 = blockIdx.x * 128;

    {
        const int r = tid >> 1, hf = tid & 1;
        const uint4* sh = (const uint4*)(Xh + (size_t)(n0 + r) * 64 + hf * 32);
        const uint4* sl = (const uint4*)(Xl + (size_t)(n0 + r) * 64 + hf * 32);
        char* dh_ = smc + F_AH + r * 144 + hf * 64;
        char* dl_ = smc + F_AL + r * 144 + hf * 64;
        #pragma unroll
        for (int i = 0; i < 4; i++) {
            *(uint4*)(dh_ + i * 16) = sh[i];
            *(uint4*)(dl_ + i * 16) = sl[i];
        }
    }
    {
        const uint4* sh = (const uint4*)(g_ph + tid * 64);
        const uint4* sl = (const uint4*)(g_pl + tid * 64);
        char* dh_ = smc + F_BH + tid * 144;
        char* dl_ = smc + F_BL + tid * 144;
        #pragma unroll
        for (int i = 0; i < 8; i++) {
            *(uint4*)(dh_ + i * 16) = sh[i];
            *(uint4*)(dl_ + i * 16) = sl[i];
        }
    }
    if (IS_Q) {
        const int b = n0 >> 16;
        const float4* src = (const float4*)(k1 + b * 4096);
        float4* dst = (float4*)(smc + F_K1);
        #pragma unroll
        for (int j = 0; j < 4; j++)
            dst[tid * 4 + j] = src[tid * 4 + j];
    }
    __syncthreads();

    if (tid < 128) {
        const __nv_bfloat162* ph = (const __nv_bfloat162*)(smc + F_AH + tid * 144);
        const __nv_bfloat162* pl = (const __nv_bfloat162*)(smc + F_AL + tid * 144);
        float ss = 0.f;
        #pragma unroll
        for (int i = 0; i < 32; i++) {
            float2 h = __bfloat1622float2(ph[i]);
            float2 l = __bfloat1622float2(pl[i]);
            float x0 = h.x + l.x, x1 = h.y + l.y;
            ss = fmaf(x0, x0, ss);
            ss = fmaf(x1, x1, ss);
        }
        ((float*)(smc + F_DG))[tid] = 0.0625f * ss;
    }
    __syncthreads();

    const int part = lane >> 3, l8 = lane & 7;
    const int aRow = (part & 1) * 8 + l8, aCol = (part >> 1) * 8;
    const int bRow = (part >> 1) * 8 + l8, bCol = (part & 1) * 8;

    float acc[32][4];
    #pragma unroll
    for (int i = 0; i < 32; i++)
        #pragma unroll
        for (int j = 0; j < 4; j++) acc[i][j] = 0.f;

    #pragma unroll
    for (int ks = 0; ks < 4; ks++) {
        uint32_t ah[4], al[4];
        const uint32_t aoff = (uint32_t)((16 * w + aRow) * 144 + (ks * 16 + aCol) * 2);
        ldm4(ah, smb + F_AH + aoff);
        ldm4(al, smb + F_AL + aoff);
        #pragma unroll
        for (int p = 0; p < 16; p++) {
            uint32_t bh[4], bl[4];
            const uint32_t boff = (uint32_t)((p * 16 + bRow) * 144 + (ks * 16 + bCol) * 2);
            ldm4(bh, smb + F_BH + boff);
            ldm4(bl, smb + F_BL + boff);
            mma16816(acc[2 * p],     ah, &bh[0]);
            mma16816(acc[2 * p],     ah, &bl[0]);
            mma16816(acc[2 * p],     al, &bh[0]);
            mma16816(acc[2 * p + 1], ah, &bh[2]);
            mma16816(acc[2 * p + 1], ah, &bl[2]);
            mma16816(acc[2 * p + 1], al, &bh[2]);
        }
    }

    const int g = lane >> 2, cc = (lane & 3) * 2;
    const int lr0 = 16 * w + g;
    const float d0 = ((float*)(smc + F_DG))[lr0];
    const float d1 = ((float*)(smc + F_DG))[lr0 + 8];

    if (IS_Q) {
        float m0 = -3.0e38f, m1 = -3.0e38f;
        #pragma unroll
        for (int nf = 0; nf < 32; nf++) {
            m0 = fmaxf(m0, fmaxf(acc[nf][0], acc[nf][1]));
            m1 = fmaxf(m1, fmaxf(acc[nf][2], acc[nf][3]));
        }
        m0 = fmaxf(m0, __shfl_xor_sync(0xffffffffu, m0, 1));
        m0 = fmaxf(m0, __shfl_xor_sync(0xffffffffu, m0, 2));
        m1 = fmaxf(m1, __shfl_xor_sync(0xffffffffu, m1, 1));
        m1 = fmaxf(m1, __shfl_xor_sync(0xffffffffu, m1, 2));
        const float s0 = d0 + m0, s1 = d1 + m1;
        const int h0 = lr0 & 15, h1 = (lr0 + 8) & 15;
        const float* k1s = (const float*)(smc + F_K1);
        float dp0 = 0.f, dp1 = 0.f;
        #pragma unroll
        for (int nf = 0; nf < 32; nf++) {
            const int col = nf * 8 + cc;
            float v0 = rbf(RATIO * (fexp(acc[nf][0] - s0) + 1e-4f));
            float v1 = rbf(RATIO * (fexp(acc[nf][1] - s0) + 1e-4f));
            float v2 = rbf(RATIO * (fexp(acc[nf][2] - s1) + 1e-4f));
            float v3 = rbf(RATIO * (fexp(acc[nf][3] - s1) + 1e-4f));
            *(uint32_t*)(out + (size_t)(n0 + lr0) * 256 + col)     = pack2(v0, v1);
            *(uint32_t*)(out + (size_t)(n0 + lr0 + 8) * 256 + col) = pack2(v2, v3);
            dp0 = fmaf(v0, k1s[h0 * 256 + col], dp0);
            dp0 = fmaf(v1, k1s[h0 * 256 + col + 1], dp0);
            dp1 = fmaf(v2, k1s[h1 * 256 + col], dp1);
            dp1 = fmaf(v3, k1s[h1 * 256 + col + 1], dp1);
        }
        dp0 += __shfl_xor_sync(0xffffffffu, dp0, 1);
        dp0 += __shfl_xor_sync(0xffffffffu, dp0, 2);
        dp1 += __shfl_xor_sync(0xffffffffu, dp1, 1);
        dp1 += __shfl_xor_sync(0xffffffffu, dp1, 2);
        if ((lane & 3) == 0) {
            den[n0 + lr0]     = dp0;
            den[n0 + lr0 + 8] = dp1;
        }
    } else {
        float wmax = -3.0e38f;
        #pragma unroll
        for (int nf = 0; nf < 32; nf++) {
            const int col = nf * 8 + cc;
            wmax = fmaxf(wmax, fmaxf(fmaxf(acc[nf][0], acc[nf][1]),
                                     fmaxf(acc[nf][2], acc[nf][3])));
            float v0 = fexp(acc[nf][0] - d0);
            float v1 = fexp(acc[nf][1] - d0);
            float v2 = fexp(acc[nf][2] - d1);
            float v3 = fexp(acc[nf][3] - d1);
            *(uint32_t*)(out + (size_t)(n0 + lr0) * 256 + col)     = pack2(v0, v1);
            *(uint32_t*)(out + (size_t)(n0 + lr0 + 8) * 256 + col) = pack2(v2, v3);
        }
        #pragma unroll
        for (int o = 16; o > 0; o >>= 1)
            wmax = fmaxf(wmax, __shfl_xor_sync(0xffffffffu, wmax, o));
        float* red = (float*)(smc + F_RD);
        if (lane == 0) red[w] = wmax;
        __syncthreads();
        if (tid == 0) {
            float m = red[0];
            #pragma unroll
            for (int i = 1; i < 8; i++) m = fmaxf(m, red[i]);
            atomicMaxF(&g_kmax, m);
        }
    }
}

// ---- kv partials on HMMA: C[256 r][64 v] = u^T @ (vh+vl) per (bh, chunk) ---
#define KVU_STR 528
#define KVV_STR 144
#define KVU_STG (16*KVU_STR)
#define KVV_STG (16*KVV_STR)
#define KV_VH0  (3*KVU_STG)
#define KV_VL0  (KV_VH0 + 3*KVV_STG)
#define KV_SMEM (KV_VL0 + 3*KVV_STG)

__global__ __launch_bounds__(256)
void k_kv()
{
    char* smc = (char*)dynsm;
    const uint32_t smb = s2u(smc);
    const int bh = blockIdx.x, c = blockIdx.y;
    const int b = bh >> 4, h = bh & 15;
    const int tid = threadIdx.x, w = tid >> 5, lane = tid & 31;
    const int sbase = b * S_ + c * SCH;

    const int urow0 = tid >> 5,       ucol0 = tid & 31;
    const int urow1 = urow0 + 8;
    const int half = tid >> 7, rem = tid & 127;
    const int vrow = rem >> 3, vq = rem & 7;
    const __nv_bfloat16* usrc0 = g_u + ((size_t)(sbase + urow0) * H_ + h) * RR + ucol0 * 8;
    const __nv_bfloat16* usrc1 = g_u + ((size_t)(sbase + urow1) * H_ + h) * RR + ucol0 * 8;
    const __nv_bfloat16* vsrc = (half ? g_vl : g_vh)
                                + (size_t)(sbase + vrow) * DM + h * DH + vq * 8;
    const uint32_t ud0 = smb + urow0 * KVU_STR + ucol0 * 16;
    const uint32_t ud1 = smb + urow1 * KVU_STR + ucol0 * 16;
    const uint32_t vd  = smb + (half ? KV_VL0 : KV_VH0) + vrow * KVV_STR + vq * 16;

    auto issue = [&](int i) {
        const int stg = i % 3;
        const size_t ua = (size_t)i * 16 * (H_ * RR);
        const size_t va = (size_t)i * 16 * DM;
        cp16(ud0 + stg * KVU_STG, usrc0 + ua);
        cp16(ud1 + stg * KVU_STG, usrc1 + ua);
        cp16(vd  + stg * KVV_STG, vsrc + va);
        asm volatile("cp.async.commit_group;");
    };
    issue(0); issue(1); issue(2);

    const int part = lane >> 3, l8 = lane & 7;
    const int a_srow = (part >> 1) * 8 + l8, a_rcol = (part & 1) * 8;
    const int b_srow = (part & 1) * 8 + l8, b_vcol = (part >> 1) * 8;

    float acc[2][8][4];
    #pragma unroll
    for (int i = 0; i < 2; i++)
        #pragma unroll
        for (int j = 0; j < 8; j++)
            #pragma unroll
            for (int k = 0; k < 4; k++) acc[i][j][k] = 0.f;
    float u1 = 0.f, v1 = 0.f;

    for (int i = 0; i < 32; i++) {
        asm volatile("cp.async.wait_group 2;");
        __syncthreads();
        const int stg = i % 3;
        const uint32_t ub  = smb + stg * KVU_STG;
        const uint32_t vhb = smb + KV_VH0 + stg * KVV_STG;
        const uint32_t vlb = smb + KV_VL0 + stg * KVV_STG;

        uint32_t af[2][4], bhf[4][4], blf[4][4];
        #pragma unroll
        for (int mi = 0; mi < 2; mi++)
            ldm4t(af[mi], ub + a_srow * KVU_STR + (w * 32 + mi * 16 + a_rcol) * 2);
        #pragma unroll
        for (int nb = 0; nb < 4; nb++) {
            const uint32_t off = b_srow * KVV_STR + (nb * 16 + b_vcol) * 2;
            ldm4t(bhf[nb], vhb + off);
            ldm4t(blf[nb], vlb + off);
        }
        #pragma unroll
        for (int mi = 0; mi < 2; mi++)
            #pragma unroll
            for (int ni = 0; ni < 8; ni++) {
                mma16816(acc[mi][ni], af[mi], &bhf[ni >> 1][(ni & 1) * 2]);
                mma16816(acc[mi][ni], af[mi], &blf[ni >> 1][(ni & 1) * 2]);
            }
        const char* uu = smc + stg * KVU_STG;
        #pragma unroll
        for (int s = 0; s < 16; s++)
            u1 += __bfloat162float(*(const __nv_bfloat16*)(uu + s * KVU_STR + tid * 2));
        if (tid < 64) {
            const char* vh_ = smc + KV_VH0 + stg * KVV_STG;
            const char* vl_ = smc + KV_VL0 + stg * KVV_STG;
            #pragma unroll
            for (int s = 0; s < 16; s++)
                v1 += __bfloat162float(*(const __nv_bfloat16*)(vh_ + s * KVV_STR + tid * 2))
                    + __bfloat162float(*(const __nv_bfloat16*)(vl_ + s * KVV_STR + tid * 2));
        }
        __syncthreads();
        if (i + 3 < 32) issue(i + 3);
    }

    const int g = lane >> 2, cc = (lane & 3) * 2;
    const int pb = c * BH + bh;
    float* kp = g_kvp + (size_t)pb * (RR * DH);
    #pragma unroll
    for (int mi = 0; mi < 2; mi++) {
        const int r0 = w * 32 + mi * 16 + g;
        #pragma unroll
        for (int ni = 0; ni < 8; ni++) {
            const int col = ni * 8 + cc;
            *(float2*)(kp + r0 * DH + col)       = make_float2(acc[mi][ni][0], acc[mi][ni][1]);
            *(float2*)(kp + (r0 + 8) * DH + col) = make_float2(acc[mi][ni][2], acc[mi][ni][3]);
        }
    }
    g_u1p[pb * RR + tid] = u1;
    if (tid < 64) g_v1p[pb * DH + tid] = v1;
}

__global__ void k_red()
{
    const int bh = blockIdx.x, t = threadIdx.x;
    const float a = RATIO * fexp(-g_kmax);
    float s = 0.f;
    #pragma unroll
    for (int c = 0; c < SPLIT; c++) s += g_u1p[(c * BH + bh) * RR + t];
    g_k1[bh * RR + t] = a * s + RATIO * 1e-4f * (float)S_;
    if (t < DH) {
        float vs = 0.f;
        #pragma unroll
        for (int c = 0; c < SPLIT; c++) vs += g_v1p[(c * BH + bh) * DH + t];
        g_v1[bh * DH + t] = vs;
    }
}

__global__ void k_kvred()
{
    const int bh = blockIdx.x, r = blockIdx.y, v = threadIdx.x;
    const float a = RATIO * fexp(-g_kmax);
    float s = 0.f;
    #pragma unroll
    for (int c = 0; c < SPLIT; c++)
        s += g_kvp[((size_t)(c * BH + bh) * RR + r) * DH + v];
    const float val = a * s + RATIO * 1e-4f * g_v1[bh * DH + v];
    const float hv = rbf(val);
    g_kvfh[(size_t)bh * (DH * RR) + v * RR + r] = __float2bfloat16(hv);
    g_kvfl[(size_t)bh * (DH * RR) + v * RR + r] = __float2bfloat16(val - hv);
}

// ---- attention out on HMMA: qhat[128,256] @ kvfT[256,64], /den, bf16 hi/lo --
#define AT_A  0
#define AT_BH (128 * 528)
#define AT_BL (AT_BH + 64 * 528)
#define AT_SMEM (AT_BL + 64 * 528)

__global__ __launch_bounds__(256)
void k_att()
{
    char* smc = (char*)dynsm;
    const uint32_t smb = s2u(smc);
    const int bh = blockIdx.x, sc = blockIdx.y;
    const int b = bh >> 4, h = bh & 15;
    const int tid = threadIdx.x, w = tid >> 5, lane = tid & 31;

    #pragma unroll
    for (int t = 0; t < 16; t++) {
        const int idx = tid + t * 256;
        const int row = idx >> 5, col = idx & 31;
        cp16(smb + AT_A + row * 528 + col * 16,
             g_qhat + ((size_t)(b * S_ + sc * 128 + row) * H_ + h) * RR + col * 8);
    }
    #pragma unroll
    for (int t = 0; t < 16; t++) {
        const int idx = tid + t * 256;
        const int hf = idx >> 11, rem = idx & 2047;
        const int row = rem >> 5, col = rem & 31;
        cp16(smb + (hf ? AT_BL : AT_BH) + row * 528 + col * 16,
             (hf ? g_kvfl : g_kvfh) + (size_t)bh * (DH * RR) + row * RR + col * 8);
    }
    asm volatile("cp.async.commit_group;");
    asm volatile("cp.async.wait_group 0;");
    __syncthreads();

    const int part = lane >> 3, l8 = lane & 7;
    const int aRow = (part & 1) * 8 + l8, aCol = (part >> 1) * 8;
    const int bRow = (part >> 1) * 8 + l8, bCol = (part & 1) * 8;

    float acc[8][4];
    #pragma unroll
    for (int i = 0; i < 8; i++)
        #pragma unroll
        for (int j = 0; j < 4; j++) acc[i][j] = 0.f;

    #pragma unroll
    for (int kk = 0; kk < 16; kk++) {
        uint32_t af[4];
        ldm4(af, smb + AT_A + (w * 16 + aRow) * 528 + (kk * 16 + aCol) * 2);
        uint32_t bhf[4][4], blf[4][4];
        #pragma unroll
        for (int nb = 0; nb < 4; nb++) {
            const uint32_t off = (nb * 16 + bRow) * 528 + (kk * 16 + bCol) * 2;
            ldm4(bhf[nb], smb + AT_BH + off);
            ldm4(blf[nb], smb + AT_BL + off);
        }
        #pragma unroll
        for (int ni = 0; ni < 8; ni++) {
            mma16816(acc[ni], af, &bhf[ni >> 1][(ni & 1) * 2]);
            mma16816(acc[ni], af, &blf[ni >> 1][(ni & 1) * 2]);
        }
    }

    const int g = lane >> 2, cc = (lane & 3) * 2;
    #pragma unroll
    for (int hf = 0; hf < 2; hf++) {
        const int s = sc * 128 + w * 16 + g + hf * 8;
        const int n = (b * S_ + s) * H_ + h;
        const float inv = 1.0f / g_den[n];
        const size_t ob = (size_t)(b * S_ + s) * DM + h * DH;
        #pragma unroll
        for (int ni = 0; ni < 8; ni++) {
            const int col = ni * 8 + cc;
            const float v0 = acc[ni][hf * 2] * inv;
            const float v1 = acc[ni][hf * 2 + 1] * inv;
            const float h0 = rbf(v0), h1 = rbf(v1);
            *(uint32_t*)(g_ah + ob + col) = pack2(h0, h1);
            *(uint32_t*)(g_al + ob + col) = pack2(v0 - h0, v1 - h1);
        }
    }
}

// ---------------------------------------------------------------------------
extern "C" void kernel_launch(void* const* d_in, const int* in_sizes, int n_in,
                              void* d_out, int out_size)
{
    const float* query = (const float*)d_in[0];
    const float* key   = (const float*)d_in[1];
    const float* value = (const float*)d_in[2];
    const float* Wq    = (const float*)d_in[3];
    const float* bq    = (const float*)d_in[4];
    const float* Wk    = (const float*)d_in[5];
    const float* bk    = (const float*)d_in[6];
    const float* Wv    = (const float*)d_in[7];
    const float* bv    = (const float*)d_in[8];
    const float* Wo    = (const float*)d_in[9];
    const float* bo    = (const float*)d_in[10];
    const float* proj  = (const float*)d_in[11];
    float* out = (float*)d_out;

    void *pvh, *pvl, *pqh, *pql, *pkh, *pkl, *pqf, *pu, *pk1, *pden,
         *pah, *pal, *pwh, *pwl;
    cudaGetSymbolAddress(&pvh, g_vh);
    cudaGetSymbolAddress(&pvl, g_vl);
    cudaGetSymbolAddress(&pqh, g_qh);
    cudaGetSymbolAddress(&pql, g_ql);
    cudaGetSymbolAddress(&pkh, g_kh);
    cudaGetSymbolAddress(&pkl, g_kl);
    cudaGetSymbolAddress(&pqf, g_qhat);
    cudaGetSymbolAddress(&pu,  g_u);
    cudaGetSymbolAddress(&pk1, g_k1);
    cudaGetSymbolAddress(&pden, g_den);
    cudaGetSymbolAddress(&pah, g_ah);
    cudaGetSymbolAddress(&pal, g_al);
    cudaGetSymbolAddress(&pwh, g_wh);
    cudaGetSymbolAddress(&pwl, g_wl);

    cudaFuncSetAttribute(k_mm<0>, cudaFuncAttributeMaxDynamicSharedMemorySize, MM_SMEM);
    cudaFuncSetAttribute(k_mm<1>, cudaFuncAttributeMaxDynamicSharedMemorySize, MM_SMEM);
    cudaFuncSetAttribute(k_featm<true>,  cudaFuncAttributeMaxDynamicSharedMemorySize, FEATM_SMEM);
    cudaFuncSetAttribute(k_featm<false>, cudaFuncAttributeMaxDynamicSharedMemorySize, FEATM_SMEM);
    cudaFuncSetAttribute(k_kv, cudaFuncAttributeMaxDynamicSharedMemorySize, KV_SMEM);
    cudaFuncSetAttribute(k_att, cudaFuncAttributeMaxDynamicSharedMemorySize, AT_SMEM);

    __nv_bfloat16* ah = (__nv_bfloat16*)pah;
    __nv_bfloat16* al = (__nv_bfloat16*)pal;
    __nv_bfloat16* wh = (__nv_bfloat16*)pwh;
    __nv_bfloat16* wl = (__nv_bfloat16*)pwl;

    const int CVT_G = MROWS * DM / 4 / 256;
    const dim3 WT_G(DM / 32, DM / 32);
    const dim3 WT_B(32, 8);
    const dim3 MM_G(DM / 128, MROWS / 128);

    k_init<<<1, 1>>>();
    k_cvt_proj<<<64, 256>>>(proj);

    // Q = query @ Wq + bq  -> split bf16
    k_cvt_act<<<CVT_G, 256>>>((const float4*)query, (uint2*)ah, (uint2*)al);
    k_cvt_wt<<<WT_G, WT_B>>>(Wq, wh, wl);
    k_mm<1><<<MM_G, 256, MM_SMEM>>>(ah, al, wh, wl, bq, nullptr,
                                    (__nv_bfloat16*)pqh, (__nv_bfloat16*)pql);
    // K = key @ Wk + bk  -> split bf16
    k_cvt_act<<<CVT_G, 256>>>((const float4*)key, (uint2*)ah, (uint2*)al);
    k_cvt_wt<<<WT_G, WT_B>>>(Wk, wh, wl);
    k_mm<1><<<MM_G, 256, MM_SMEM>>>(ah, al, wh, wl, bk, nullptr,
                                    (__nv_bfloat16*)pkh, (__nv_bfloat16*)pkl);
    // V = value @ Wv + bv -> split bf16
    k_cvt_act<<<CVT_G, 256>>>((const float4*)value, (uint2*)ah, (uint2*)al);
    k_cvt_wt<<<WT_G, WT_B>>>(Wv, wh, wl);
    k_mm<1><<<MM_G, 256, MM_SMEM>>>(ah, al, wh, wl, bv, nullptr,
                                    (__nv_bfloat16*)pvh, (__nv_bfloat16*)pvl);

    // key feature path first
    k_featm<false><<<NROWS / 128, 256, FEATM_SMEM>>>(
        (const __nv_bfloat16*)pkh, (const __nv_bfloat16*)pkl,
        (__nv_bfloat16*)pu, nullptr, nullptr);
    k_kv<<<dim3(BH, SPLIT), 256, KV_SMEM>>>();
    k_red<<<BH, 256>>>();
    k_kvred<<<dim3(BH, RR), DH>>>();

    k_featm<true><<<NROWS / 128, 256, FEATM_SMEM>>>(
        (const __nv_bfloat16*)pqh, (const __nv_bfloat16*)pql,
        (__nv_bfloat16*)pqf, (const float*)pk1, (float*)pden);
    k_att<<<dim3(BH, S_ / 128), 256, AT_SMEM>>>();

    // out = att @ Wo + bo
    k_cvt_wt<<<WT_G, WT_B>>>(Wo, wh, wl);
    k_mm<0><<<MM_G, 256, MM_SMEM>>>(ah, al, wh, wl, bo, out, nullptr, nullptr);
}